// round 10
// baseline (speedup 1.0000x reference)
#include <cuda_runtime.h>
#include <cuda_bf16.h>
#include <math.h>
#include <stdint.h>

// Problem constants
constexpr int Bc = 4, Tc = 4096, Dc = 1024, Hc = 16, HDc = 64;
constexpr int BT = Bc * Tc;          // 16384 rows
constexpr int BH = Bc * Hc;          // 64 (b,h) pairs
constexpr int SPLIT = 32;            // T-split for kv reduction

// Scratch (device globals: no allocation allowed in kernel_launch)
__device__ float g_q[BT * Dc];
__device__ float g_k[BT * Dc];
__device__ float g_v[BT * Dc];
__device__ float g_kvp[BH * SPLIT * HDc * HDc];
__device__ float g_ksp[BH * SPLIT * HDc];
__device__ float g_kv[BH * HDc * HDc];
__device__ float g_ksum[BH * HDc];
__device__ unsigned char g_mask[BT];
// bf16 hi/lo split operand buffers
__device__ __nv_bfloat16 g_xh[BT * Dc], g_xl[BT * Dc];
__device__ __nv_bfloat16 g_ah[BT * Dc], g_al[BT * Dc];
__device__ __nv_bfloat16 g_wh[4][Dc * Dc], g_wl[4][Dc * Dc];

__device__ __forceinline__ float phi(float x) {
    return x > 0.f ? x + 1.f : expf(x);
}

__device__ __forceinline__ uint32_t smem_u32(const void* p) {
    uint32_t a;
    asm("{ .reg .u64 t; cvta.to.shared.u64 t, %1; cvt.u32.u64 %0, t; }" : "=r"(a) : "l"(p));
    return a;
}

// pack two bf16 (from floats) into u32: x low, y high
__device__ __forceinline__ uint32_t pack_bf2(float x, float y) {
    __nv_bfloat162 h = __floats2bfloat162_rn(x, y);
    return *(uint32_t*)&h;
}

__device__ __forceinline__ void cp16(uint32_t dst, const void* src) {
    asm volatile("cp.async.cg.shared.global [%0], [%1], 16;" :: "r"(dst), "l"(src));
}
#define CP_COMMIT() asm volatile("cp.async.commit_group;" ::: "memory")
#define CP_WAIT1()  asm volatile("cp.async.wait_group 1;" ::: "memory")
#define CP_WAIT0()  asm volatile("cp.async.wait_group 0;" ::: "memory")

// ---------------------------------------------------------------------------
// fp32 -> (hi, lo) bf16 split, vectorized
// ---------------------------------------------------------------------------
__global__ __launch_bounds__(256) void split_kernel(
    const float4* __restrict__ src, uint2* __restrict__ hi, uint2* __restrict__ lo, int n4)
{
    for (int i = blockIdx.x * 256 + threadIdx.x; i < n4; i += gridDim.x * 256) {
        float4 v = src[i];
        float hx = __bfloat162float(__float2bfloat16(v.x));
        float hy = __bfloat162float(__float2bfloat16(v.y));
        float hz = __bfloat162float(__float2bfloat16(v.z));
        float hw = __bfloat162float(__float2bfloat16(v.w));
        hi[i] = make_uint2(pack_bf2(v.x, v.y), pack_bf2(v.z, v.w));
        lo[i] = make_uint2(pack_bf2(v.x - hx, v.y - hy), pack_bf2(v.z - hz, v.w - hw));
    }
}

// all 4 weight matrices in one launch (blockIdx.y = which W)
__global__ __launch_bounds__(256) void splitw_kernel(
    const float4* __restrict__ w0, const float4* __restrict__ w1,
    const float4* __restrict__ w2, const float4* __restrict__ w3)
{
    const int wsel = blockIdx.y;
    const float4* src = wsel == 0 ? w0 : wsel == 1 ? w1 : wsel == 2 ? w2 : w3;
    uint2* hi = (uint2*)(g_wh[wsel]);
    uint2* lo = (uint2*)(g_wl[wsel]);
    const int n4 = Dc * Dc / 4;
    for (int i = blockIdx.x * 256 + threadIdx.x; i < n4; i += gridDim.x * 256) {
        float4 v = src[i];
        float hx = __bfloat162float(__float2bfloat16(v.x));
        float hy = __bfloat162float(__float2bfloat16(v.y));
        float hz = __bfloat162float(__float2bfloat16(v.z));
        float hw = __bfloat162float(__float2bfloat16(v.w));
        hi[i] = make_uint2(pack_bf2(v.x, v.y), pack_bf2(v.z, v.w));
        lo[i] = make_uint2(pack_bf2(v.x - hx, v.y - hy), pack_bf2(v.z - hz, v.w - hw));
    }
}

// ---------------------------------------------------------------------------
// 3-term bf16-split tensor-core GEMM, operands pre-split in global bf16.
// C[M,N] = A @ B^T, M=16384, N=K=1024. Tile 128x128, 8 warps (4m x 2n),
// warp tile 32x64, mma.m16n8k16.bf16, cp.async 3-stage pipeline, 2 CTAs/SM.
// ldmatrix swizzled offsets decomposed into loop-invariant registers:
//   addr = stage_base + row*128 + (col ^ (lrow<<4))    [row&7 == lrow always]
// op: 0 none, 1 phi, 2 phi+mask, 3 mask
// ---------------------------------------------------------------------------
constexpr int GSM_STAGE = 32768;
constexpr int NSTAGES = 3;
constexpr int GSM_TOTAL = NSTAGES * GSM_STAGE;   // 96KB -> 2 CTAs/SM

__global__ __launch_bounds__(256, 2) void gemm_tc_kernel(
    const __nv_bfloat16* __restrict__ Ah, const __nv_bfloat16* __restrict__ Al,
    const __nv_bfloat16* __restrict__ Bh, const __nv_bfloat16* __restrict__ Bl,
    float* __restrict__ C, const unsigned char* __restrict__ mask, int op)
{
    extern __shared__ __align__(1024) char smem[];
    const uint32_t sbase = smem_u32(smem);
    const int tid = threadIdx.x;
    const int wid = tid >> 5, lane = tid & 31;
    const int wm = wid & 3, wn = wid >> 2;
    const int brow = blockIdx.y, bcol = blockIdx.x;

    // loader mapping: each thread owns (part, ci) and 4 rows r0+32i for A and B
    const int r0 = tid >> 3;            // 0..31
    const int part = (tid >> 2) & 1;    // 0 = hi, 1 = lo
    const int ci = tid & 3;             // 16B chunk within 64B half-row
    const __nv_bfloat16* srcA = (part ? Al : Ah) + (size_t)(brow * 128) * 1024;
    const __nv_bfloat16* srcB = (part ? Bl : Bh) + (size_t)(bcol * 128) * 1024;
    uint32_t dstA[4];
#pragma unroll
    for (int i = 0; i < 4; i++) {
        int row = r0 + 32 * i;
        dstA[i] = ((uint32_t)(row * 128 + part * 64 + ci * 16)) ^ (uint32_t)((row & 7) << 4);
    }

    auto load_stage = [&](int s, int buf) {
        uint32_t sb = sbase + buf * GSM_STAGE;
        const int koff = s * 32 + ci * 8;
#pragma unroll
        for (int i = 0; i < 4; i++) {
            int row = r0 + 32 * i;
            cp16(sb + dstA[i], srcA + (size_t)row * 1024 + koff);
            cp16(sb + 16384 + dstA[i], srcB + (size_t)row * 1024 + koff);
        }
    };

    // prologue: stages 0..1
#pragma unroll
    for (int s = 0; s < NSTAGES - 1; s++) {
        load_stage(s, s);
        CP_COMMIT();
    }

    float acc[2][8][4];
#pragma unroll
    for (int mt = 0; mt < 2; mt++)
#pragma unroll
        for (int nt = 0; nt < 8; nt++)
#pragma unroll
            for (int j = 0; j < 4; j++) acc[mt][nt][j] = 0.f;

    const int lrow = lane & 7;
    const int seg = lane >> 3;
    const int segr = (seg & 1) << 3;
    const int segc = (seg & 2) << 3;

    // ---- loop-invariant ldmatrix offset registers ----
    const uint32_t swl = (uint32_t)(lrow << 4);
    uint32_t rowA[2], rowB[4], cxH[2], cxL[2];
#pragma unroll
    for (int mt = 0; mt < 2; mt++)
        rowA[mt] = (uint32_t)((wm * 32 + mt * 16 + lrow + segr) * 128);
#pragma unroll
    for (int n = 0; n < 4; n++)
        rowB[n] = (uint32_t)((wn * 64 + n * 16 + lrow + segr) * 128);
#pragma unroll
    for (int ks2 = 0; ks2 < 2; ks2++) {
        cxH[ks2] = ((uint32_t)(ks2 * 32 + segc)) ^ swl;
        cxL[ks2] = ((uint32_t)(64 + ks2 * 32 + segc)) ^ swl;
    }

    constexpr int NT = 32;
    int buf = 0;
#pragma unroll 1
    for (int t = 0; t < NT; t++) {
        CP_WAIT1();
        __syncthreads();
        if (t + NSTAGES - 1 < NT) {
            int lb = buf + NSTAGES - 1; if (lb >= NSTAGES) lb -= NSTAGES;
            load_stage(t + NSTAGES - 1, lb);
        }
        CP_COMMIT();

        const uint32_t sA = sbase + buf * GSM_STAGE;
        const uint32_t sB = sA + 16384;
        if (++buf == NSTAGES) buf = 0;

#pragma unroll
        for (int ks2 = 0; ks2 < 2; ks2++) {
            // ---- load ALL fragments for this half-stage up front ----
            uint32_t afrH[2][4], afrL[2][4];
#pragma unroll
            for (int mt = 0; mt < 2; mt++) {
                asm volatile("ldmatrix.sync.aligned.m8n8.x4.shared.b16 {%0,%1,%2,%3}, [%4];"
                    : "=r"(afrH[mt][0]), "=r"(afrH[mt][1]), "=r"(afrH[mt][2]), "=r"(afrH[mt][3])
                    : "r"(sA + rowA[mt] + cxH[ks2]));
                asm volatile("ldmatrix.sync.aligned.m8n8.x4.shared.b16 {%0,%1,%2,%3}, [%4];"
                    : "=r"(afrL[mt][0]), "=r"(afrL[mt][1]), "=r"(afrL[mt][2]), "=r"(afrL[mt][3])
                    : "r"(sA + rowA[mt] + cxL[ks2]));
            }
            uint32_t bfrH[4][4], bfrL[4][4];
#pragma unroll
            for (int nt2 = 0; nt2 < 4; nt2++) {
                asm volatile("ldmatrix.sync.aligned.m8n8.x4.shared.b16 {%0,%1,%2,%3}, [%4];"
                    : "=r"(bfrH[nt2][0]), "=r"(bfrH[nt2][1]), "=r"(bfrH[nt2][2]), "=r"(bfrH[nt2][3])
                    : "r"(sB + rowB[nt2] + cxH[ks2]));
                asm volatile("ldmatrix.sync.aligned.m8n8.x4.shared.b16 {%0,%1,%2,%3}, [%4];"
                    : "=r"(bfrL[nt2][0]), "=r"(bfrL[nt2][1]), "=r"(bfrL[nt2][2]), "=r"(bfrL[nt2][3])
                    : "r"(sB + rowB[nt2] + cxL[ks2]));
            }

            // ---- 48 MMAs, no intervening smem ops ----
#pragma unroll
            for (int mt = 0; mt < 2; mt++)
#pragma unroll
                for (int nt = 0; nt < 8; nt++) {
                    const int g = nt >> 1, h = nt & 1;
                    asm volatile(
                        "mma.sync.aligned.m16n8k16.row.col.f32.bf16.bf16.f32 "
                        "{%0,%1,%2,%3}, {%4,%5,%6,%7}, {%8,%9}, {%0,%1,%2,%3};"
                        : "+f"(acc[mt][nt][0]), "+f"(acc[mt][nt][1]),
                          "+f"(acc[mt][nt][2]), "+f"(acc[mt][nt][3])
                        : "r"(afrH[mt][0]), "r"(afrH[mt][1]), "r"(afrH[mt][2]), "r"(afrH[mt][3]),
                          "r"(bfrH[g][h]), "r"(bfrH[g][h + 2]));
                    asm volatile(
                        "mma.sync.aligned.m16n8k16.row.col.f32.bf16.bf16.f32 "
                        "{%0,%1,%2,%3}, {%4,%5,%6,%7}, {%8,%9}, {%0,%1,%2,%3};"
                        : "+f"(acc[mt][nt][0]), "+f"(acc[mt][nt][1]),
                          "+f"(acc[mt][nt][2]), "+f"(acc[mt][nt][3])
                        : "r"(afrL[mt][0]), "r"(afrL[mt][1]), "r"(afrL[mt][2]), "r"(afrL[mt][3]),
                          "r"(bfrH[g][h]), "r"(bfrH[g][h + 2]));
                    asm volatile(
                        "mma.sync.aligned.m16n8k16.row.col.f32.bf16.bf16.f32 "
                        "{%0,%1,%2,%3}, {%4,%5,%6,%7}, {%8,%9}, {%0,%1,%2,%3};"
                        : "+f"(acc[mt][nt][0]), "+f"(acc[mt][nt][1]),
                          "+f"(acc[mt][nt][2]), "+f"(acc[mt][nt][3])
                        : "r"(afrH[mt][0]), "r"(afrH[mt][1]), "r"(afrH[mt][2]), "r"(afrH[mt][3]),
                          "r"(bfrL[g][h]), "r"(bfrL[g][h + 2]));
                }
        }
    }

    // Epilogue
    const int r0e = brow * 128 + wm * 32 + (lane >> 2);
    const int c0 = bcol * 128 + wn * 64 + (lane & 3) * 2;
    const bool do_phi = (op == 1 || op == 2);
    const bool do_msk = (op >= 2);
#pragma unroll
    for (int mt = 0; mt < 2; mt++) {
        const int r = r0e + mt * 16;
        const bool mz0 = do_msk && (mask[r] != 0);
        const bool mz1 = do_msk && (mask[r + 8] != 0);
#pragma unroll
        for (int nt = 0; nt < 8; nt++) {
            float2 v0 = make_float2(acc[mt][nt][0], acc[mt][nt][1]);
            float2 v1 = make_float2(acc[mt][nt][2], acc[mt][nt][3]);
            if (do_phi) {
                v0.x = phi(v0.x); v0.y = phi(v0.y);
                v1.x = phi(v1.x); v1.y = phi(v1.y);
            }
            if (mz0) { v0.x = 0.f; v0.y = 0.f; }
            if (mz1) { v1.x = 0.f; v1.y = 0.f; }
            *(float2*)(C + (size_t)r * 1024 + c0 + nt * 8) = v0;
            *(float2*)(C + (size_t)(r + 8) * 1024 + c0 + nt * 8) = v1;
        }
    }
}

// ---------------------------------------------------------------------------
// Mask normalization (dtype-agnostic) -> uint8 0/1
// ---------------------------------------------------------------------------
__global__ __launch_bounds__(256) void mask_convert_kernel(const unsigned char* __restrict__ mraw)
{
    __shared__ int s_float, s_odd;
    if (threadIdx.x == 0) { s_float = 0; s_odd = 0; }
    __syncthreads();
    for (int i = threadIdx.x; i < 4096; i += 256) {
        unsigned char v = mraw[i];
        if (v == 0x3F) s_float = 1;
        if (v != 0 && (i & 3) != 0) s_odd = 1;
    }
    __syncthreads();
    const int dtype = s_float ? 2 : (s_odd ? 0 : 1);

    const int m0 = blockIdx.x * 256 + threadIdx.x;
    for (int m = m0; m < BT; m += 64 * 256) {
        unsigned char r;
        if (dtype == 0)      r = (mraw[m] != 0);
        else if (dtype == 1) r = (((const int*)mraw)[m] != 0);
        else                 r = (((const float*)mraw)[m] != 0.0f);
        g_mask[m] = r;
    }
}

// ---------------------------------------------------------------------------
// kv partial: for (b,h,split): kv[d][e] += k[t,d]*v[t,e]; ksum[d] += k[t,d]
// cp.async double-buffered 32-row chunks. grid (BH, SPLIT), 256 threads.
// ---------------------------------------------------------------------------
__global__ __launch_bounds__(256) void kv_partial_kernel()
{
    const int tid = threadIdx.x;
    const int bh = blockIdx.x, sy = blockIdx.y;
    const int b = bh >> 4, h = bh & 15;
    const int t0 = sy * (Tc / SPLIT);    // 128 rows per block

    __shared__ __align__(16) float Ks[2][32][64];
    __shared__ __align__(16) float Vs[2][32][64];
    const uint32_t sK = smem_u32(&Ks[0][0][0]);
    const uint32_t sV = smem_u32(&Vs[0][0][0]);

    float acc[16];
#pragma unroll
    for (int j = 0; j < 16; j++) acc[j] = 0.f;
    float ks = 0.f;

    const int d = tid >> 2;
    const int eb = (tid & 3) * 16;
    const size_t base = ((size_t)b * Tc) * Dc + h * 64;

    // loader: slots tid and tid+256 (512 float4 slots per 8KB buffer)
    const int tl0 = tid >> 4,         c40 = (tid & 15) * 4;
    const int tl1 = (tid + 256) >> 4, c41 = ((tid + 256) & 15) * 4;
    const uint32_t so0 = (uint32_t)((tl0 * 64 + c40) * 4);
    const uint32_t so1 = (uint32_t)((tl1 * 64 + c41) * 4);

    auto load_chunk = [&](int c, int bufsel) {
        uint32_t kb = sK + bufsel * 8192, vb = sV + bufsel * 8192;
        size_t g0 = base + (size_t)(t0 + c * 32 + tl0) * Dc + c40;
        size_t g1 = base + (size_t)(t0 + c * 32 + tl1) * Dc + c41;
        cp16(kb + so0, g_k + g0);
        cp16(vb + so0, g_v + g0);
        cp16(kb + so1, g_k + g1);
        cp16(vb + so1, g_v + g1);
    };

    load_chunk(0, 0);
    CP_COMMIT();

#pragma unroll 1
    for (int c = 0; c < 4; c++) {
        if (c < 3) {
            load_chunk(c + 1, (c + 1) & 1);
            CP_COMMIT();
            CP_WAIT1();
        } else {
            CP_WAIT0();
        }
        __syncthreads();
        const int cb = c & 1;
#pragma unroll
        for (int t = 0; t < 32; t++) {
            float kd = Ks[cb][t][d];
            ks += kd;
            float4 v0 = *(const float4*)&Vs[cb][t][eb];
            float4 v1 = *(const float4*)&Vs[cb][t][eb + 4];
            float4 v2 = *(const float4*)&Vs[cb][t][eb + 8];
            float4 v3 = *(const float4*)&Vs[cb][t][eb + 12];
            acc[0]  = fmaf(kd, v0.x, acc[0]);  acc[1]  = fmaf(kd, v0.y, acc[1]);
            acc[2]  = fmaf(kd, v0.z, acc[2]);  acc[3]  = fmaf(kd, v0.w, acc[3]);
            acc[4]  = fmaf(kd, v1.x, acc[4]);  acc[5]  = fmaf(kd, v1.y, acc[5]);
            acc[6]  = fmaf(kd, v1.z, acc[6]);  acc[7]  = fmaf(kd, v1.w, acc[7]);
            acc[8]  = fmaf(kd, v2.x, acc[8]);  acc[9]  = fmaf(kd, v2.y, acc[9]);
            acc[10] = fmaf(kd, v2.z, acc[10]); acc[11] = fmaf(kd, v2.w, acc[11]);
            acc[12] = fmaf(kd, v3.x, acc[12]); acc[13] = fmaf(kd, v3.y, acc[13]);
            acc[14] = fmaf(kd, v3.z, acc[14]); acc[15] = fmaf(kd, v3.w, acc[15]);
        }
        __syncthreads();
    }

    float* outp = g_kvp + ((size_t)(bh * SPLIT + sy)) * 4096 + d * 64 + eb;
    *(float4*)(outp + 0)  = make_float4(acc[0], acc[1], acc[2], acc[3]);
    *(float4*)(outp + 4)  = make_float4(acc[4], acc[5], acc[6], acc[7]);
    *(float4*)(outp + 8)  = make_float4(acc[8], acc[9], acc[10], acc[11]);
    *(float4*)(outp + 12) = make_float4(acc[12], acc[13], acc[14], acc[15]);
    if ((tid & 3) == 0)
        g_ksp[(bh * SPLIT + sy) * 64 + d] = ks;
}

// ---------------------------------------------------------------------------
__global__ __launch_bounds__(256) void kv_reduce_kernel()
{
    const int bh = blockIdx.x, tid = threadIdx.x;
#pragma unroll
    for (int j = 0; j < 4; j++) {
        int off = tid * 16 + j * 4;
        float4 s = make_float4(0.f, 0.f, 0.f, 0.f);
#pragma unroll
        for (int sp = 0; sp < SPLIT; sp++) {
            float4 p = *(const float4*)(g_kvp + ((size_t)(bh * SPLIT + sp)) * 4096 + off);
            s.x += p.x; s.y += p.y; s.z += p.z; s.w += p.w;
        }
        *(float4*)(g_kv + (size_t)bh * 4096 + off) = s;
    }
    if (tid < 64) {
        float s = 0.f;
#pragma unroll
        for (int sp = 0; sp < SPLIT; sp++)
            s += g_ksp[(bh * SPLIT + sp) * 64 + tid];
        g_ksum[bh * 64 + tid] = s;
    }
}

// ---------------------------------------------------------------------------
// attn out: out[t,e] = (sum_d q[t,d]*kv[d,e]) / max(q[t]·ksum, 1e-6)
// Writes bf16 hi/lo split directly (input of the final GEMM).
// ---------------------------------------------------------------------------
__global__ __launch_bounds__(256) void attn_out_kernel()
{
    const int tid = threadIdx.x;
    const int bh = blockIdx.y;
    const int b = bh >> 4, h = bh & 15;
    const int t0 = blockIdx.x * 64;

    __shared__ __align__(16) float KV[4096];
    __shared__ float Qs[64][65];
    __shared__ float Ksm[64];

#pragma unroll
    for (int j = 0; j < 4; j++) {
        int f = tid + j * 256;
        *(float4*)&KV[f * 4] = *(const float4*)(g_kv + (size_t)bh * 4096 + f * 4);
    }
    if (tid < 64) Ksm[tid] = g_ksum[bh * 64 + tid];

    const size_t base = ((size_t)b * Tc) * Dc + h * 64;
#pragma unroll
    for (int j = 0; j < 16; j++) {
        int i = tid + j * 256;
        int tl = i >> 6, d = i & 63;
        Qs[d][tl] = g_q[base + (size_t)(t0 + tl) * Dc + d];
    }
    __syncthreads();

    const int tl = tid >> 2;
    const int eb = (tid & 3) * 16;
    float acc[16];
#pragma unroll
    for (int j = 0; j < 16; j++) acc[j] = 0.f;
    float nrm = 0.f;

#pragma unroll
    for (int d2 = 0; d2 < 64; d2++) {
        float qd = Qs[d2][tl];
        nrm = fmaf(qd, Ksm[d2], nrm);
        const float4* kvp = (const float4*)&KV[d2 * 64 + eb];
        float4 v0 = kvp[0], v1 = kvp[1], v2 = kvp[2], v3 = kvp[3];
        acc[0]  = fmaf(qd, v0.x, acc[0]);  acc[1]  = fmaf(qd, v0.y, acc[1]);
        acc[2]  = fmaf(qd, v0.z, acc[2]);  acc[3]  = fmaf(qd, v0.w, acc[3]);
        acc[4]  = fmaf(qd, v1.x, acc[4]);  acc[5]  = fmaf(qd, v1.y, acc[5]);
        acc[6]  = fmaf(qd, v1.z, acc[6]);  acc[7]  = fmaf(qd, v1.w, acc[7]);
        acc[8]  = fmaf(qd, v2.x, acc[8]);  acc[9]  = fmaf(qd, v2.y, acc[9]);
        acc[10] = fmaf(qd, v2.z, acc[10]); acc[11] = fmaf(qd, v2.w, acc[11]);
        acc[12] = fmaf(qd, v3.x, acc[12]); acc[13] = fmaf(qd, v3.y, acc[13]);
        acc[14] = fmaf(qd, v3.z, acc[14]); acc[15] = fmaf(qd, v3.w, acc[15]);
    }

    float inv = 1.f / fmaxf(nrm, 1e-6f);
    const size_t idx = base + (size_t)(t0 + tl) * Dc + eb;
#pragma unroll
    for (int j = 0; j < 4; j++) {
        float a0 = acc[j * 4 + 0] * inv, a1 = acc[j * 4 + 1] * inv;
        float a2 = acc[j * 4 + 2] * inv, a3 = acc[j * 4 + 3] * inv;
        float h0 = __bfloat162float(__float2bfloat16(a0));
        float h1 = __bfloat162float(__float2bfloat16(a1));
        float h2 = __bfloat162float(__float2bfloat16(a2));
        float h3 = __bfloat162float(__float2bfloat16(a3));
        *(uint2*)(g_ah + idx + j * 4) = make_uint2(pack_bf2(a0, a1), pack_bf2(a2, a3));
        *(uint2*)(g_al + idx + j * 4) = make_uint2(pack_bf2(a0 - h0, a1 - h1),
                                                   pack_bf2(a2 - h2, a3 - h3));
    }
}

// ---------------------------------------------------------------------------
extern "C" void kernel_launch(void* const* d_in, const int* in_sizes, int n_in,
                              void* d_out, int out_size)
{
    const float* x          = (const float*)d_in[0];
    const unsigned char* mk = (const unsigned char*)d_in[1];
    float* out              = (float*)d_out;

    float *qp, *kp, *vp;
    unsigned char* mkc;
    __nv_bfloat16 *xh, *xl, *ah, *al, *wh, *wl;
    cudaGetSymbolAddress((void**)&qp, g_q);
    cudaGetSymbolAddress((void**)&kp, g_k);
    cudaGetSymbolAddress((void**)&vp, g_v);
    cudaGetSymbolAddress((void**)&mkc, g_mask);
    cudaGetSymbolAddress((void**)&xh, g_xh);
    cudaGetSymbolAddress((void**)&xl, g_xl);
    cudaGetSymbolAddress((void**)&ah, g_ah);
    cudaGetSymbolAddress((void**)&al, g_al);
    cudaGetSymbolAddress((void**)&wh, g_wh);
    cudaGetSymbolAddress((void**)&wl, g_wl);

    cudaFuncSetAttribute(gemm_tc_kernel,
                         cudaFuncAttributeMaxDynamicSharedMemorySize, GSM_TOTAL);

    // Launch order chosen so ncu (-s 5 -c 1) profiles a GEMM (6th launch).
    split_kernel<<<4096, 256>>>((const float4*)x, (uint2*)xh, (uint2*)xl, BT * Dc / 4);      // 1
    splitw_kernel<<<dim3(512, 4), 256>>>((const float4*)d_in[2], (const float4*)d_in[3],
                                         (const float4*)d_in[4], (const float4*)d_in[5]);    // 2
    mask_convert_kernel<<<64, 256>>>(mk);                                                    // 3

    dim3 ggrid(Dc / 128, BT / 128);   // (8, 128)
    gemm_tc_kernel<<<ggrid, 256, GSM_TOTAL>>>(xh, xl, wh + 0 * (size_t)Dc * Dc, wl + 0 * (size_t)Dc * Dc, qp, mkc, 1);  // 4
    gemm_tc_kernel<<<ggrid, 256, GSM_TOTAL>>>(xh, xl, wh + 1 * (size_t)Dc * Dc, wl + 1 * (size_t)Dc * Dc, kp, mkc, 2);  // 5
    gemm_tc_kernel<<<ggrid, 256, GSM_TOTAL>>>(xh, xl, wh + 2 * (size_t)Dc * Dc, wl + 2 * (size_t)Dc * Dc, vp, mkc, 3);  // 6 <- profiled
    kv_partial_kernel<<<dim3(BH, SPLIT), 256>>>();
    kv_reduce_kernel<<<BH, 256>>>();
    attn_out_kernel<<<dim3(Tc / 64, BH), 256>>>();
    gemm_tc_kernel<<<ggrid, 256, GSM_TOTAL>>>(ah, al, wh + 3 * (size_t)Dc * Dc, wl + 3 * (size_t)Dc * Dc, out, mkc, 0);
}

// round 11
// speedup vs baseline: 1.2138x; 1.2138x over previous
#include <cuda_runtime.h>
#include <cuda_bf16.h>
#include <math.h>
#include <stdint.h>

// Problem constants
constexpr int Bc = 4, Tc = 4096, Dc = 1024, Hc = 16, HDc = 64;
constexpr int BT = Bc * Tc;          // 16384 rows
constexpr int BH = Bc * Hc;          // 64 (b,h) pairs
constexpr int SPLIT = 32;            // total kv partial slots (8 blocks x 4 groups)

// Scratch (device globals: no allocation allowed in kernel_launch)
__device__ float g_q[BT * Dc];
__device__ float g_k[BT * Dc];
__device__ float g_v[BT * Dc];
__device__ float g_kvp[BH * SPLIT * HDc * HDc];
__device__ float g_ksp[BH * SPLIT * HDc];
__device__ float g_kv[BH * HDc * HDc];
__device__ float g_ksum[BH * HDc];
__device__ unsigned char g_mask[BT];
// bf16 hi/lo split operand buffers
__device__ __nv_bfloat16 g_xh[BT * Dc], g_xl[BT * Dc];
__device__ __nv_bfloat16 g_ah[BT * Dc], g_al[BT * Dc];
__device__ __nv_bfloat16 g_wh[4][Dc * Dc], g_wl[4][Dc * Dc];

__device__ __forceinline__ float phi(float x) {
    return x > 0.f ? x + 1.f : expf(x);
}

__device__ __forceinline__ uint32_t smem_u32(const void* p) {
    uint32_t a;
    asm("{ .reg .u64 t; cvta.to.shared.u64 t, %1; cvt.u32.u64 %0, t; }" : "=r"(a) : "l"(p));
    return a;
}

// pack two bf16 (from floats) into u32: x low, y high
__device__ __forceinline__ uint32_t pack_bf2(float x, float y) {
    __nv_bfloat162 h = __floats2bfloat162_rn(x, y);
    return *(uint32_t*)&h;
}

__device__ __forceinline__ void cp16(uint32_t dst, const void* src) {
    asm volatile("cp.async.cg.shared.global [%0], [%1], 16;" :: "r"(dst), "l"(src));
}
#define CP_COMMIT() asm volatile("cp.async.commit_group;" ::: "memory")
#define CP_WAIT1()  asm volatile("cp.async.wait_group 1;" ::: "memory")
#define CP_WAIT0()  asm volatile("cp.async.wait_group 0;" ::: "memory")

// ---------------------------------------------------------------------------
// fp32 -> (hi, lo) bf16 split, vectorized
// ---------------------------------------------------------------------------
__global__ __launch_bounds__(256) void split_kernel(
    const float4* __restrict__ src, uint2* __restrict__ hi, uint2* __restrict__ lo, int n4)
{
    for (int i = blockIdx.x * 256 + threadIdx.x; i < n4; i += gridDim.x * 256) {
        float4 v = src[i];
        float hx = __bfloat162float(__float2bfloat16(v.x));
        float hy = __bfloat162float(__float2bfloat16(v.y));
        float hz = __bfloat162float(__float2bfloat16(v.z));
        float hw = __bfloat162float(__float2bfloat16(v.w));
        hi[i] = make_uint2(pack_bf2(v.x, v.y), pack_bf2(v.z, v.w));
        lo[i] = make_uint2(pack_bf2(v.x - hx, v.y - hy), pack_bf2(v.z - hz, v.w - hw));
    }
}

// all 4 weight matrices in one launch (blockIdx.y = which W)
__global__ __launch_bounds__(256) void splitw_kernel(
    const float4* __restrict__ w0, const float4* __restrict__ w1,
    const float4* __restrict__ w2, const float4* __restrict__ w3)
{
    const int wsel = blockIdx.y;
    const float4* src = wsel == 0 ? w0 : wsel == 1 ? w1 : wsel == 2 ? w2 : w3;
    uint2* hi = (uint2*)(g_wh[wsel]);
    uint2* lo = (uint2*)(g_wl[wsel]);
    const int n4 = Dc * Dc / 4;
    for (int i = blockIdx.x * 256 + threadIdx.x; i < n4; i += gridDim.x * 256) {
        float4 v = src[i];
        float hx = __bfloat162float(__float2bfloat16(v.x));
        float hy = __bfloat162float(__float2bfloat16(v.y));
        float hz = __bfloat162float(__float2bfloat16(v.z));
        float hw = __bfloat162float(__float2bfloat16(v.w));
        hi[i] = make_uint2(pack_bf2(v.x, v.y), pack_bf2(v.z, v.w));
        lo[i] = make_uint2(pack_bf2(v.x - hx, v.y - hy), pack_bf2(v.z - hz, v.w - hw));
    }
}

// ---------------------------------------------------------------------------
// 3-term bf16-split tensor-core GEMM (unchanged from R10 measurement point).
// ---------------------------------------------------------------------------
constexpr int GSM_STAGE = 32768;
constexpr int NSTAGES = 3;
constexpr int GSM_TOTAL = NSTAGES * GSM_STAGE;   // 96KB -> 2 CTAs/SM

__global__ __launch_bounds__(256, 2) void gemm_tc_kernel(
    const __nv_bfloat16* __restrict__ Ah, const __nv_bfloat16* __restrict__ Al,
    const __nv_bfloat16* __restrict__ Bh, const __nv_bfloat16* __restrict__ Bl,
    float* __restrict__ C, const unsigned char* __restrict__ mask, int op)
{
    extern __shared__ __align__(1024) char smem[];
    const uint32_t sbase = smem_u32(smem);
    const int tid = threadIdx.x;
    const int wid = tid >> 5, lane = tid & 31;
    const int wm = wid & 3, wn = wid >> 2;
    const int brow = blockIdx.y, bcol = blockIdx.x;

    const int r0 = tid >> 3;
    const int part = (tid >> 2) & 1;
    const int ci = tid & 3;
    const __nv_bfloat16* srcA = (part ? Al : Ah) + (size_t)(brow * 128) * 1024;
    const __nv_bfloat16* srcB = (part ? Bl : Bh) + (size_t)(bcol * 128) * 1024;
    uint32_t dstA[4];
#pragma unroll
    for (int i = 0; i < 4; i++) {
        int row = r0 + 32 * i;
        dstA[i] = ((uint32_t)(row * 128 + part * 64 + ci * 16)) ^ (uint32_t)((row & 7) << 4);
    }

    auto load_stage = [&](int s, int buf) {
        uint32_t sb = sbase + buf * GSM_STAGE;
        const int koff = s * 32 + ci * 8;
#pragma unroll
        for (int i = 0; i < 4; i++) {
            int row = r0 + 32 * i;
            cp16(sb + dstA[i], srcA + (size_t)row * 1024 + koff);
            cp16(sb + 16384 + dstA[i], srcB + (size_t)row * 1024 + koff);
        }
    };

#pragma unroll
    for (int s = 0; s < NSTAGES - 1; s++) {
        load_stage(s, s);
        CP_COMMIT();
    }

    float acc[2][8][4];
#pragma unroll
    for (int mt = 0; mt < 2; mt++)
#pragma unroll
        for (int nt = 0; nt < 8; nt++)
#pragma unroll
            for (int j = 0; j < 4; j++) acc[mt][nt][j] = 0.f;

    const int lrow = lane & 7;
    const int seg = lane >> 3;
    const int segr = (seg & 1) << 3;
    const int segc = (seg & 2) << 3;

    const uint32_t swl = (uint32_t)(lrow << 4);
    uint32_t rowA[2], rowB[4], cxH[2], cxL[2];
#pragma unroll
    for (int mt = 0; mt < 2; mt++)
        rowA[mt] = (uint32_t)((wm * 32 + mt * 16 + lrow + segr) * 128);
#pragma unroll
    for (int n = 0; n < 4; n++)
        rowB[n] = (uint32_t)((wn * 64 + n * 16 + lrow + segr) * 128);
#pragma unroll
    for (int ks2 = 0; ks2 < 2; ks2++) {
        cxH[ks2] = ((uint32_t)(ks2 * 32 + segc)) ^ swl;
        cxL[ks2] = ((uint32_t)(64 + ks2 * 32 + segc)) ^ swl;
    }

    constexpr int NT = 32;
    int buf = 0;
#pragma unroll 1
    for (int t = 0; t < NT; t++) {
        CP_WAIT1();
        __syncthreads();
        if (t + NSTAGES - 1 < NT) {
            int lb = buf + NSTAGES - 1; if (lb >= NSTAGES) lb -= NSTAGES;
            load_stage(t + NSTAGES - 1, lb);
        }
        CP_COMMIT();

        const uint32_t sA = sbase + buf * GSM_STAGE;
        const uint32_t sB = sA + 16384;
        if (++buf == NSTAGES) buf = 0;

#pragma unroll
        for (int ks2 = 0; ks2 < 2; ks2++) {
            uint32_t afrH[2][4], afrL[2][4];
#pragma unroll
            for (int mt = 0; mt < 2; mt++) {
                asm volatile("ldmatrix.sync.aligned.m8n8.x4.shared.b16 {%0,%1,%2,%3}, [%4];"
                    : "=r"(afrH[mt][0]), "=r"(afrH[mt][1]), "=r"(afrH[mt][2]), "=r"(afrH[mt][3])
                    : "r"(sA + rowA[mt] + cxH[ks2]));
                asm volatile("ldmatrix.sync.aligned.m8n8.x4.shared.b16 {%0,%1,%2,%3}, [%4];"
                    : "=r"(afrL[mt][0]), "=r"(afrL[mt][1]), "=r"(afrL[mt][2]), "=r"(afrL[mt][3])
                    : "r"(sA + rowA[mt] + cxL[ks2]));
            }
            uint32_t bfrH[4][4], bfrL[4][4];
#pragma unroll
            for (int nt2 = 0; nt2 < 4; nt2++) {
                asm volatile("ldmatrix.sync.aligned.m8n8.x4.shared.b16 {%0,%1,%2,%3}, [%4];"
                    : "=r"(bfrH[nt2][0]), "=r"(bfrH[nt2][1]), "=r"(bfrH[nt2][2]), "=r"(bfrH[nt2][3])
                    : "r"(sB + rowB[nt2] + cxH[ks2]));
                asm volatile("ldmatrix.sync.aligned.m8n8.x4.shared.b16 {%0,%1,%2,%3}, [%4];"
                    : "=r"(bfrL[nt2][0]), "=r"(bfrL[nt2][1]), "=r"(bfrL[nt2][2]), "=r"(bfrL[nt2][3])
                    : "r"(sB + rowB[nt2] + cxL[ks2]));
            }

#pragma unroll
            for (int mt = 0; mt < 2; mt++)
#pragma unroll
                for (int nt = 0; nt < 8; nt++) {
                    const int g = nt >> 1, h = nt & 1;
                    asm volatile(
                        "mma.sync.aligned.m16n8k16.row.col.f32.bf16.bf16.f32 "
                        "{%0,%1,%2,%3}, {%4,%5,%6,%7}, {%8,%9}, {%0,%1,%2,%3};"
                        : "+f"(acc[mt][nt][0]), "+f"(acc[mt][nt][1]),
                          "+f"(acc[mt][nt][2]), "+f"(acc[mt][nt][3])
                        : "r"(afrH[mt][0]), "r"(afrH[mt][1]), "r"(afrH[mt][2]), "r"(afrH[mt][3]),
                          "r"(bfrH[g][h]), "r"(bfrH[g][h + 2]));
                    asm volatile(
                        "mma.sync.aligned.m16n8k16.row.col.f32.bf16.bf16.f32 "
                        "{%0,%1,%2,%3}, {%4,%5,%6,%7}, {%8,%9}, {%0,%1,%2,%3};"
                        : "+f"(acc[mt][nt][0]), "+f"(acc[mt][nt][1]),
                          "+f"(acc[mt][nt][2]), "+f"(acc[mt][nt][3])
                        : "r"(afrL[mt][0]), "r"(afrL[mt][1]), "r"(afrL[mt][2]), "r"(afrL[mt][3]),
                          "r"(bfrH[g][h]), "r"(bfrH[g][h + 2]));
                    asm volatile(
                        "mma.sync.aligned.m16n8k16.row.col.f32.bf16.bf16.f32 "
                        "{%0,%1,%2,%3}, {%4,%5,%6,%7}, {%8,%9}, {%0,%1,%2,%3};"
                        : "+f"(acc[mt][nt][0]), "+f"(acc[mt][nt][1]),
                          "+f"(acc[mt][nt][2]), "+f"(acc[mt][nt][3])
                        : "r"(afrH[mt][0]), "r"(afrH[mt][1]), "r"(afrH[mt][2]), "r"(afrH[mt][3]),
                          "r"(bfrL[g][h]), "r"(bfrL[g][h + 2]));
                }
        }
    }

    // Epilogue
    const int r0e = brow * 128 + wm * 32 + (lane >> 2);
    const int c0 = bcol * 128 + wn * 64 + (lane & 3) * 2;
    const bool do_phi = (op == 1 || op == 2);
    const bool do_msk = (op >= 2);
#pragma unroll
    for (int mt = 0; mt < 2; mt++) {
        const int r = r0e + mt * 16;
        const bool mz0 = do_msk && (mask[r] != 0);
        const bool mz1 = do_msk && (mask[r + 8] != 0);
#pragma unroll
        for (int nt = 0; nt < 8; nt++) {
            float2 v0 = make_float2(acc[mt][nt][0], acc[mt][nt][1]);
            float2 v1 = make_float2(acc[mt][nt][2], acc[mt][nt][3]);
            if (do_phi) {
                v0.x = phi(v0.x); v0.y = phi(v0.y);
                v1.x = phi(v1.x); v1.y = phi(v1.y);
            }
            if (mz0) { v0.x = 0.f; v0.y = 0.f; }
            if (mz1) { v1.x = 0.f; v1.y = 0.f; }
            *(float2*)(C + (size_t)r * 1024 + c0 + nt * 8) = v0;
            *(float2*)(C + (size_t)(r + 8) * 1024 + c0 + nt * 8) = v1;
        }
    }
}

// ---------------------------------------------------------------------------
// Mask normalization (dtype-agnostic) -> uint8 0/1
// ---------------------------------------------------------------------------
__global__ __launch_bounds__(256) void mask_convert_kernel(const unsigned char* __restrict__ mraw)
{
    __shared__ int s_float, s_odd;
    if (threadIdx.x == 0) { s_float = 0; s_odd = 0; }
    __syncthreads();
    for (int i = threadIdx.x; i < 4096; i += 256) {
        unsigned char v = mraw[i];
        if (v == 0x3F) s_float = 1;
        if (v != 0 && (i & 3) != 0) s_odd = 1;
    }
    __syncthreads();
    const int dtype = s_float ? 2 : (s_odd ? 0 : 1);

    const int m0 = blockIdx.x * 256 + threadIdx.x;
    for (int m = m0; m < BT; m += 64 * 256) {
        unsigned char r;
        if (dtype == 0)      r = (mraw[m] != 0);
        else if (dtype == 1) r = (((const int*)mraw)[m] != 0);
        else                 r = (((const float*)mraw)[m] != 0.0f);
        g_mask[m] = r;
    }
}

// ---------------------------------------------------------------------------
// kv partial, register-blocked 4d x 16e per thread.
// grid (BH, 8), 256 threads = 4 t-groups x 64 threads.
// Group q handles rows [c*32 + q*8, c*32 + q*8 + 8) of each 32-row chunk and
// writes partial slot bh*32 + sy*4 + q (32 slots total, kv_reduce unchanged).
// ---------------------------------------------------------------------------
__global__ __launch_bounds__(256) void kv_partial_kernel()
{
    const int tid = threadIdx.x;
    const int bh = blockIdx.x, sy = blockIdx.y;
    const int b = bh >> 4, h = bh & 15;
    const int t0 = sy * 512;

    __shared__ __align__(16) float Ks[2][32][64];
    __shared__ __align__(16) float Vs[2][32][64];
    const uint32_t sK = smem_u32(&Ks[0][0][0]);
    const uint32_t sV = smem_u32(&Vs[0][0][0]);

    const int q  = tid >> 6;           // t-group 0..3
    const int r  = tid & 63;
    const int d0 = (r >> 2) * 4;       // 0..60
    const int e0 = (r & 3) * 16;       // 0,16,32,48

    float acc[4][16];
#pragma unroll
    for (int j = 0; j < 4; j++)
#pragma unroll
        for (int i = 0; i < 16; i++) acc[j][i] = 0.f;
    float ks[4] = {0.f, 0.f, 0.f, 0.f};

    const size_t base = ((size_t)b * Tc) * Dc + h * 64;

    // loader: slots tid and tid+256 (512 float4 slots per 8KB buffer)
    const int tl0 = tid >> 4,         c40 = (tid & 15) * 4;
    const int tl1 = (tid + 256) >> 4, c41 = ((tid + 256) & 15) * 4;
    const uint32_t so0 = (uint32_t)((tl0 * 64 + c40) * 4);
    const uint32_t so1 = (uint32_t)((tl1 * 64 + c41) * 4);

    auto load_chunk = [&](int c, int bufsel) {
        uint32_t kb = sK + bufsel * 8192, vb = sV + bufsel * 8192;
        size_t g0 = base + (size_t)(t0 + c * 32 + tl0) * Dc + c40;
        size_t g1 = base + (size_t)(t0 + c * 32 + tl1) * Dc + c41;
        cp16(kb + so0, g_k + g0);
        cp16(vb + so0, g_v + g0);
        cp16(kb + so1, g_k + g1);
        cp16(vb + so1, g_v + g1);
    };

    load_chunk(0, 0);
    CP_COMMIT();

#pragma unroll 1
    for (int c = 0; c < 16; c++) {
        if (c < 15) {
            load_chunk(c + 1, (c + 1) & 1);
            CP_COMMIT();
            CP_WAIT1();
        } else {
            CP_WAIT0();
        }
        __syncthreads();
        const int cb = c & 1;
#pragma unroll
        for (int tt = 0; tt < 8; tt++) {
            const int t = q * 8 + tt;
            float4 kd = *(const float4*)&Ks[cb][t][d0];
            float4 v0 = *(const float4*)&Vs[cb][t][e0];
            float4 v1 = *(const float4*)&Vs[cb][t][e0 + 4];
            float4 v2 = *(const float4*)&Vs[cb][t][e0 + 8];
            float4 v3 = *(const float4*)&Vs[cb][t][e0 + 12];
            ks[0] += kd.x; ks[1] += kd.y; ks[2] += kd.z; ks[3] += kd.w;
            const float kv4[4] = {kd.x, kd.y, kd.z, kd.w};
            const float vv[16] = {v0.x, v0.y, v0.z, v0.w, v1.x, v1.y, v1.z, v1.w,
                                  v2.x, v2.y, v2.z, v2.w, v3.x, v3.y, v3.z, v3.w};
#pragma unroll
            for (int j = 0; j < 4; j++)
#pragma unroll
                for (int i = 0; i < 16; i++)
                    acc[j][i] = fmaf(kv4[j], vv[i], acc[j][i]);
        }
        __syncthreads();
    }

    const int slot = bh * SPLIT + sy * 4 + q;
    float* outp = g_kvp + (size_t)slot * 4096;
#pragma unroll
    for (int j = 0; j < 4; j++) {
        float* rp = outp + (d0 + j) * 64 + e0;
        *(float4*)(rp + 0)  = make_float4(acc[j][0], acc[j][1], acc[j][2], acc[j][3]);
        *(float4*)(rp + 4)  = make_float4(acc[j][4], acc[j][5], acc[j][6], acc[j][7]);
        *(float4*)(rp + 8)  = make_float4(acc[j][8], acc[j][9], acc[j][10], acc[j][11]);
        *(float4*)(rp + 12) = make_float4(acc[j][12], acc[j][13], acc[j][14], acc[j][15]);
    }
    if ((r & 3) == 0) {
#pragma unroll
        for (int j = 0; j < 4; j++)
            g_ksp[slot * 64 + d0 + j] = ks[j];
    }
}

// ---------------------------------------------------------------------------
__global__ __launch_bounds__(256) void kv_reduce_kernel()
{
    const int bh = blockIdx.x, tid = threadIdx.x;
#pragma unroll
    for (int j = 0; j < 4; j++) {
        int off = tid * 16 + j * 4;
        float4 s = make_float4(0.f, 0.f, 0.f, 0.f);
#pragma unroll
        for (int sp = 0; sp < SPLIT; sp++) {
            float4 p = *(const float4*)(g_kvp + ((size_t)(bh * SPLIT + sp)) * 4096 + off);
            s.x += p.x; s.y += p.y; s.z += p.z; s.w += p.w;
        }
        *(float4*)(g_kv + (size_t)bh * 4096 + off) = s;
    }
    if (tid < 64) {
        float s = 0.f;
#pragma unroll
        for (int sp = 0; sp < SPLIT; sp++)
            s += g_ksp[(bh * SPLIT + sp) * 64 + tid];
        g_ksum[bh * 64 + tid] = s;
    }
}

// ---------------------------------------------------------------------------
// attn out, register-blocked: thread owns 4 t-rows x 16 e-cols.
// grid (Tc/256, BH), 256 threads. Q staged as [d][t] chunks (16 d at a time)
// so the 4 rows load as one LDS.128; KV row reused across 4 rows.
// Writes bf16 hi/lo split directly.
// ---------------------------------------------------------------------------
constexpr int QS_STRIDE = 260;

__global__ __launch_bounds__(256) void attn_out_kernel()
{
    const int tid = threadIdx.x;
    const int bh = blockIdx.y;
    const int b = bh >> 4, h = bh & 15;
    const int t0 = blockIdx.x * 256;

    __shared__ __align__(16) float KV[4096];            // 16KB [d][e]
    __shared__ __align__(16) float Qs[16][QS_STRIDE];   // 16.6KB [d][t]
    __shared__ float Ksm[64];

#pragma unroll
    for (int j = 0; j < 4; j++) {
        int f = tid + j * 256;
        *(float4*)&KV[f * 4] = *(const float4*)(g_kv + (size_t)bh * 4096 + f * 4);
    }
    if (tid < 64) Ksm[tid] = g_ksum[bh * 64 + tid];

    const size_t base = ((size_t)b * Tc) * Dc + h * 64;
    const int tl4 = tid >> 2;          // 0..63 -> rows t0 + tl4*4 .. +3
    const int e0 = (tid & 3) * 16;

    float acc[4][16];
#pragma unroll
    for (int j = 0; j < 4; j++)
#pragma unroll
        for (int i = 0; i < 16; i++) acc[j][i] = 0.f;
    float nrm[4] = {0.f, 0.f, 0.f, 0.f};

#pragma unroll 1
    for (int dc = 0; dc < 4; dc++) {
        __syncthreads();
        // stage Q chunk: Qs[d][t] = q[t0+t][dc*16+d]
#pragma unroll
        for (int j = 0; j < 16; j++) {
            int idx = tid + j * 256;         // 0..4095
            int d = idx & 15, t = idx >> 4;
            Qs[d][t] = g_q[base + (size_t)(t0 + t) * Dc + dc * 16 + d];
        }
        __syncthreads();
#pragma unroll
        for (int d2 = 0; d2 < 16; d2++) {
            const int dg = dc * 16 + d2;
            float4 qv = *(const float4*)&Qs[d2][tl4 * 4];
            const float km = Ksm[dg];
            const float4* kvp = (const float4*)&KV[dg * 64 + e0];
            float4 w0 = kvp[0], w1 = kvp[1], w2 = kvp[2], w3 = kvp[3];
            const float qq[4] = {qv.x, qv.y, qv.z, qv.w};
            const float vv[16] = {w0.x, w0.y, w0.z, w0.w, w1.x, w1.y, w1.z, w1.w,
                                  w2.x, w2.y, w2.z, w2.w, w3.x, w3.y, w3.z, w3.w};
#pragma unroll
            for (int j = 0; j < 4; j++) {
                nrm[j] = fmaf(qq[j], km, nrm[j]);
#pragma unroll
                for (int i = 0; i < 16; i++)
                    acc[j][i] = fmaf(qq[j], vv[i], acc[j][i]);
            }
        }
    }

#pragma unroll
    for (int j = 0; j < 4; j++) {
        const float inv = 1.f / fmaxf(nrm[j], 1e-6f);
        const size_t idx = base + (size_t)(t0 + tl4 * 4 + j) * Dc + e0;
#pragma unroll
        for (int g = 0; g < 4; g++) {
            float a0 = acc[j][g * 4 + 0] * inv, a1 = acc[j][g * 4 + 1] * inv;
            float a2 = acc[j][g * 4 + 2] * inv, a3 = acc[j][g * 4 + 3] * inv;
            float h0 = __bfloat162float(__float2bfloat16(a0));
            float h1 = __bfloat162float(__float2bfloat16(a1));
            float h2 = __bfloat162float(__float2bfloat16(a2));
            float h3 = __bfloat162float(__float2bfloat16(a3));
            *(uint2*)(g_ah + idx + g * 4) = make_uint2(pack_bf2(a0, a1), pack_bf2(a2, a3));
            *(uint2*)(g_al + idx + g * 4) = make_uint2(pack_bf2(a0 - h0, a1 - h1),
                                                       pack_bf2(a2 - h2, a3 - h3));
        }
    }
}

// ---------------------------------------------------------------------------
extern "C" void kernel_launch(void* const* d_in, const int* in_sizes, int n_in,
                              void* d_out, int out_size)
{
    const float* x          = (const float*)d_in[0];
    const unsigned char* mk = (const unsigned char*)d_in[1];
    float* out              = (float*)d_out;

    float *qp, *kp, *vp;
    unsigned char* mkc;
    __nv_bfloat16 *xh, *xl, *ah, *al, *wh, *wl;
    cudaGetSymbolAddress((void**)&qp, g_q);
    cudaGetSymbolAddress((void**)&kp, g_k);
    cudaGetSymbolAddress((void**)&vp, g_v);
    cudaGetSymbolAddress((void**)&mkc, g_mask);
    cudaGetSymbolAddress((void**)&xh, g_xh);
    cudaGetSymbolAddress((void**)&xl, g_xl);
    cudaGetSymbolAddress((void**)&ah, g_ah);
    cudaGetSymbolAddress((void**)&al, g_al);
    cudaGetSymbolAddress((void**)&wh, g_wh);
    cudaGetSymbolAddress((void**)&wl, g_wl);

    cudaFuncSetAttribute(gemm_tc_kernel,
                         cudaFuncAttributeMaxDynamicSharedMemorySize, GSM_TOTAL);

    // Launch order chosen so ncu (-s 5 -c 1) profiles a GEMM (6th launch).
    split_kernel<<<4096, 256>>>((const float4*)x, (uint2*)xh, (uint2*)xl, BT * Dc / 4);      // 1
    splitw_kernel<<<dim3(512, 4), 256>>>((const float4*)d_in[2], (const float4*)d_in[3],
                                         (const float4*)d_in[4], (const float4*)d_in[5]);    // 2
    mask_convert_kernel<<<64, 256>>>(mk);                                                    // 3

    dim3 ggrid(Dc / 128, BT / 128);   // (8, 128)
    gemm_tc_kernel<<<ggrid, 256, GSM_TOTAL>>>(xh, xl, wh + 0 * (size_t)Dc * Dc, wl + 0 * (size_t)Dc * Dc, qp, mkc, 1);  // 4
    gemm_tc_kernel<<<ggrid, 256, GSM_TOTAL>>>(xh, xl, wh + 1 * (size_t)Dc * Dc, wl + 1 * (size_t)Dc * Dc, kp, mkc, 2);  // 5
    gemm_tc_kernel<<<ggrid, 256, GSM_TOTAL>>>(xh, xl, wh + 2 * (size_t)Dc * Dc, wl + 2 * (size_t)Dc * Dc, vp, mkc, 3);  // 6 <- profiled
    kv_partial_kernel<<<dim3(BH, 8), 256>>>();
    kv_reduce_kernel<<<BH, 256>>>();
    attn_out_kernel<<<dim3(Tc / 256, BH), 256>>>();
    gemm_tc_kernel<<<ggrid, 256, GSM_TOTAL>>>(ah, al, wh + 3 * (size_t)Dc * Dc, wl + 3 * (size_t)Dc * Dc, out, mkc, 0);
}

// round 12
// speedup vs baseline: 1.2262x; 1.0102x over previous
#include <cuda_runtime.h>
#include <cuda_bf16.h>
#include <math.h>
#include <stdint.h>

// Problem constants
constexpr int Bc = 4, Tc = 4096, Dc = 1024, Hc = 16, HDc = 64;
constexpr int BT = Bc * Tc;          // 16384 rows
constexpr int BH = Bc * Hc;          // 64 (b,h) pairs
constexpr int SPLIT = 32;            // total kv partial slots (8 blocks x 4 groups)

// Scratch (device globals: no allocation allowed in kernel_launch)
__device__ float g_q[BT * Dc];
__device__ float g_k[BT * Dc];
__device__ float g_v[BT * Dc];
__device__ float g_kvp[BH * SPLIT * HDc * HDc];
__device__ float g_ksp[BH * SPLIT * HDc];
__device__ float g_kv[BH * HDc * HDc];
__device__ float g_ksum[BH * HDc];
__device__ unsigned char g_mask[BT];
// bf16 hi/lo split operand buffers
__device__ __nv_bfloat16 g_xh[BT * Dc], g_xl[BT * Dc];
__device__ __nv_bfloat16 g_ah[BT * Dc], g_al[BT * Dc];
__device__ __nv_bfloat16 g_wh[4][Dc * Dc], g_wl[4][Dc * Dc];

__device__ __forceinline__ float phi(float x) {
    return x > 0.f ? x + 1.f : expf(x);
}

__device__ __forceinline__ uint32_t smem_u32(const void* p) {
    uint32_t a;
    asm("{ .reg .u64 t; cvta.to.shared.u64 t, %1; cvt.u32.u64 %0, t; }" : "=r"(a) : "l"(p));
    return a;
}

__device__ __forceinline__ uint32_t pack_bf2(float x, float y) {
    __nv_bfloat162 h = __floats2bfloat162_rn(x, y);
    return *(uint32_t*)&h;
}

__device__ __forceinline__ void cp16(uint32_t dst, const void* src) {
    asm volatile("cp.async.cg.shared.global [%0], [%1], 16;" :: "r"(dst), "l"(src));
}
#define CP_COMMIT() asm volatile("cp.async.commit_group;" ::: "memory")
#define CP_WAIT1()  asm volatile("cp.async.wait_group 1;" ::: "memory")
#define CP_WAIT0()  asm volatile("cp.async.wait_group 0;" ::: "memory")

// ---------------------------------------------------------------------------
// fp32 -> (hi, lo) bf16 split, vectorized
// ---------------------------------------------------------------------------
__global__ __launch_bounds__(256) void split_kernel(
    const float4* __restrict__ src, uint2* __restrict__ hi, uint2* __restrict__ lo,
    int i0, int n4)
{
    for (int i = i0 + blockIdx.x * 256 + threadIdx.x; i < n4; i += gridDim.x * 256) {
        float4 v = src[i];
        float hx = __bfloat162float(__float2bfloat16(v.x));
        float hy = __bfloat162float(__float2bfloat16(v.y));
        float hz = __bfloat162float(__float2bfloat16(v.z));
        float hw = __bfloat162float(__float2bfloat16(v.w));
        hi[i] = make_uint2(pack_bf2(v.x, v.y), pack_bf2(v.z, v.w));
        lo[i] = make_uint2(pack_bf2(v.x - hx, v.y - hy), pack_bf2(v.z - hz, v.w - hw));
    }
}

// two weight matrices per launch (blockIdx.y = which of the pair)
__global__ __launch_bounds__(256) void splitw_kernel(
    const float4* __restrict__ wa, const float4* __restrict__ wb, int wbase)
{
    const int wsel = wbase + blockIdx.y;
    const float4* src = blockIdx.y == 0 ? wa : wb;
    uint2* hi = (uint2*)(g_wh[wsel]);
    uint2* lo = (uint2*)(g_wl[wsel]);
    const int n4 = Dc * Dc / 4;
    for (int i = blockIdx.x * 256 + threadIdx.x; i < n4; i += gridDim.x * 256) {
        float4 v = src[i];
        float hx = __bfloat162float(__float2bfloat16(v.x));
        float hy = __bfloat162float(__float2bfloat16(v.y));
        float hz = __bfloat162float(__float2bfloat16(v.z));
        float hw = __bfloat162float(__float2bfloat16(v.w));
        hi[i] = make_uint2(pack_bf2(v.x, v.y), pack_bf2(v.z, v.w));
        lo[i] = make_uint2(pack_bf2(v.x - hx, v.y - hy), pack_bf2(v.z - hz, v.w - hw));
    }
}

// ---------------------------------------------------------------------------
// 3-term bf16-split tensor-core GEMM mainloop (shared by fused-QKV and Wo).
// Tile 128x128, 8 warps (4m x 2n), warp tile 32x64, cp.async 3-stage, 2 CTA/SM.
// ---------------------------------------------------------------------------
constexpr int GSM_STAGE = 32768;
constexpr int NSTAGES = 3;
constexpr int GSM_TOTAL = NSTAGES * GSM_STAGE;   // 96KB -> 2 CTAs/SM

struct GemmCore {
    float acc[2][8][4];

    __device__ __forceinline__ void run(
        uint32_t sbase, char* smem,
        const __nv_bfloat16* srcA, const __nv_bfloat16* srcB,
        int tid, int wid, int lane)
    {
        const int wm = wid & 3, wn = wid >> 2;
        const int r0 = tid >> 3;
        const int part = (tid >> 2) & 1;
        const int ci = tid & 3;
        uint32_t dstA[4];
#pragma unroll
        for (int i = 0; i < 4; i++) {
            int row = r0 + 32 * i;
            dstA[i] = ((uint32_t)(row * 128 + part * 64 + ci * 16)) ^ (uint32_t)((row & 7) << 4);
        }

        auto load_stage = [&](int s, int buf) {
            uint32_t sb = sbase + buf * GSM_STAGE;
            const int koff = s * 32 + ci * 8;
#pragma unroll
            for (int i = 0; i < 4; i++) {
                int row = r0 + 32 * i;
                cp16(sb + dstA[i], srcA + (size_t)row * 1024 + koff);
                cp16(sb + 16384 + dstA[i], srcB + (size_t)row * 1024 + koff);
            }
        };

#pragma unroll
        for (int s = 0; s < NSTAGES - 1; s++) {
            load_stage(s, s);
            CP_COMMIT();
        }

#pragma unroll
        for (int mt = 0; mt < 2; mt++)
#pragma unroll
            for (int nt = 0; nt < 8; nt++)
#pragma unroll
                for (int j = 0; j < 4; j++) acc[mt][nt][j] = 0.f;

        const int lrow = lane & 7;
        const int seg = lane >> 3;
        const int segr = (seg & 1) << 3;
        const int segc = (seg & 2) << 3;

        const uint32_t swl = (uint32_t)(lrow << 4);
        uint32_t rowA[2], rowB[4], cxH[2], cxL[2];
#pragma unroll
        for (int mt = 0; mt < 2; mt++)
            rowA[mt] = (uint32_t)((wm * 32 + mt * 16 + lrow + segr) * 128);
#pragma unroll
        for (int n = 0; n < 4; n++)
            rowB[n] = (uint32_t)((wn * 64 + n * 16 + lrow + segr) * 128);
#pragma unroll
        for (int ks2 = 0; ks2 < 2; ks2++) {
            cxH[ks2] = ((uint32_t)(ks2 * 32 + segc)) ^ swl;
            cxL[ks2] = ((uint32_t)(64 + ks2 * 32 + segc)) ^ swl;
        }

        constexpr int NT = 32;
        int buf = 0;
#pragma unroll 1
        for (int t = 0; t < NT; t++) {
            CP_WAIT1();
            __syncthreads();
            if (t + NSTAGES - 1 < NT) {
                int lb = buf + NSTAGES - 1; if (lb >= NSTAGES) lb -= NSTAGES;
                load_stage(t + NSTAGES - 1, lb);
            }
            CP_COMMIT();

            const uint32_t sA = sbase + buf * GSM_STAGE;
            const uint32_t sB = sA + 16384;
            if (++buf == NSTAGES) buf = 0;

#pragma unroll
            for (int ks2 = 0; ks2 < 2; ks2++) {
                uint32_t afrH[2][4], afrL[2][4];
#pragma unroll
                for (int mt = 0; mt < 2; mt++) {
                    asm volatile("ldmatrix.sync.aligned.m8n8.x4.shared.b16 {%0,%1,%2,%3}, [%4];"
                        : "=r"(afrH[mt][0]), "=r"(afrH[mt][1]), "=r"(afrH[mt][2]), "=r"(afrH[mt][3])
                        : "r"(sA + rowA[mt] + cxH[ks2]));
                    asm volatile("ldmatrix.sync.aligned.m8n8.x4.shared.b16 {%0,%1,%2,%3}, [%4];"
                        : "=r"(afrL[mt][0]), "=r"(afrL[mt][1]), "=r"(afrL[mt][2]), "=r"(afrL[mt][3])
                        : "r"(sA + rowA[mt] + cxL[ks2]));
                }
                uint32_t bfrH[4][4], bfrL[4][4];
#pragma unroll
                for (int nt2 = 0; nt2 < 4; nt2++) {
                    asm volatile("ldmatrix.sync.aligned.m8n8.x4.shared.b16 {%0,%1,%2,%3}, [%4];"
                        : "=r"(bfrH[nt2][0]), "=r"(bfrH[nt2][1]), "=r"(bfrH[nt2][2]), "=r"(bfrH[nt2][3])
                        : "r"(sB + rowB[nt2] + cxH[ks2]));
                    asm volatile("ldmatrix.sync.aligned.m8n8.x4.shared.b16 {%0,%1,%2,%3}, [%4];"
                        : "=r"(bfrL[nt2][0]), "=r"(bfrL[nt2][1]), "=r"(bfrL[nt2][2]), "=r"(bfrL[nt2][3])
                        : "r"(sB + rowB[nt2] + cxL[ks2]));
                }

#pragma unroll
                for (int mt = 0; mt < 2; mt++)
#pragma unroll
                    for (int nt = 0; nt < 8; nt++) {
                        const int g = nt >> 1, h = nt & 1;
                        asm volatile(
                            "mma.sync.aligned.m16n8k16.row.col.f32.bf16.bf16.f32 "
                            "{%0,%1,%2,%3}, {%4,%5,%6,%7}, {%8,%9}, {%0,%1,%2,%3};"
                            : "+f"(acc[mt][nt][0]), "+f"(acc[mt][nt][1]),
                              "+f"(acc[mt][nt][2]), "+f"(acc[mt][nt][3])
                            : "r"(afrH[mt][0]), "r"(afrH[mt][1]), "r"(afrH[mt][2]), "r"(afrH[mt][3]),
                              "r"(bfrH[g][h]), "r"(bfrH[g][h + 2]));
                        asm volatile(
                            "mma.sync.aligned.m16n8k16.row.col.f32.bf16.bf16.f32 "
                            "{%0,%1,%2,%3}, {%4,%5,%6,%7}, {%8,%9}, {%0,%1,%2,%3};"
                            : "+f"(acc[mt][nt][0]), "+f"(acc[mt][nt][1]),
                              "+f"(acc[mt][nt][2]), "+f"(acc[mt][nt][3])
                            : "r"(afrL[mt][0]), "r"(afrL[mt][1]), "r"(afrL[mt][2]), "r"(afrL[mt][3]),
                              "r"(bfrH[g][h]), "r"(bfrH[g][h + 2]));
                        asm volatile(
                            "mma.sync.aligned.m16n8k16.row.col.f32.bf16.bf16.f32 "
                            "{%0,%1,%2,%3}, {%4,%5,%6,%7}, {%8,%9}, {%0,%1,%2,%3};"
                            : "+f"(acc[mt][nt][0]), "+f"(acc[mt][nt][1]),
                              "+f"(acc[mt][nt][2]), "+f"(acc[mt][nt][3])
                            : "r"(afrH[mt][0]), "r"(afrH[mt][1]), "r"(afrH[mt][2]), "r"(afrH[mt][3]),
                              "r"(bfrL[g][h]), "r"(bfrL[g][h + 2]));
                    }
            }
        }
    }

    __device__ __forceinline__ void epilogue(
        float* C, const unsigned char* mask, int op,
        int brow, int bcol, int wid, int lane)
    {
        const int wm = wid & 3, wn = wid >> 2;
        const int r0e = brow * 128 + wm * 32 + (lane >> 2);
        const int c0 = bcol * 128 + wn * 64 + (lane & 3) * 2;
        const bool do_phi = (op == 1 || op == 2);
        const bool do_msk = (op >= 2);
#pragma unroll
        for (int mt = 0; mt < 2; mt++) {
            const int r = r0e + mt * 16;
            const bool mz0 = do_msk && (mask[r] != 0);
            const bool mz1 = do_msk && (mask[r + 8] != 0);
#pragma unroll
            for (int nt = 0; nt < 8; nt++) {
                float2 v0 = make_float2(acc[mt][nt][0], acc[mt][nt][1]);
                float2 v1 = make_float2(acc[mt][nt][2], acc[mt][nt][3]);
                if (do_phi) {
                    v0.x = phi(v0.x); v0.y = phi(v0.y);
                    v1.x = phi(v1.x); v1.y = phi(v1.y);
                }
                if (mz0) { v0.x = 0.f; v0.y = 0.f; }
                if (mz1) { v1.x = 0.f; v1.y = 0.f; }
                *(float2*)(C + (size_t)r * 1024 + c0 + nt * 8) = v0;
                *(float2*)(C + (size_t)(r + 8) * 1024 + c0 + nt * 8) = v1;
            }
        }
    }
};

// Fused Q/K/V GEMM: grid (24, 128). blockIdx.x>>3 selects W / op / output.
__global__ __launch_bounds__(256, 2) void gemm_qkv_kernel(
    const __nv_bfloat16* __restrict__ Ah, const __nv_bfloat16* __restrict__ Al,
    float* __restrict__ C0, float* __restrict__ C1, float* __restrict__ C2,
    const unsigned char* __restrict__ mask)
{
    extern __shared__ __align__(1024) char smem[];
    const uint32_t sbase = smem_u32(smem);
    const int tid = threadIdx.x;
    const int wid = tid >> 5, lane = tid & 31;
    const int brow = blockIdx.y;
    const int wsel = blockIdx.x >> 3;
    const int bcol = blockIdx.x & 7;

    const int part = (tid >> 2) & 1;
    const __nv_bfloat16* srcA = (part ? Al : Ah) + (size_t)(brow * 128) * 1024;
    const __nv_bfloat16* srcB = (part ? g_wl[wsel] : g_wh[wsel]) + (size_t)(bcol * 128) * 1024;

    GemmCore core;
    core.run(sbase, smem, srcA, srcB, tid, wid, lane);

    float* C = wsel == 0 ? C0 : wsel == 1 ? C1 : C2;
    const int op = wsel + 1;   // 1=phi(Q), 2=phi+mask(K), 3=mask(V)
    core.epilogue(C, mask, op, brow, bcol, wid, lane);
}

// Plain GEMM (used for the final Wo projection, op=0).
__global__ __launch_bounds__(256, 2) void gemm_tc_kernel(
    const __nv_bfloat16* __restrict__ Ah, const __nv_bfloat16* __restrict__ Al,
    const __nv_bfloat16* __restrict__ Bh, const __nv_bfloat16* __restrict__ Bl,
    float* __restrict__ C, const unsigned char* __restrict__ mask, int op)
{
    extern __shared__ __align__(1024) char smem[];
    const uint32_t sbase = smem_u32(smem);
    const int tid = threadIdx.x;
    const int wid = tid >> 5, lane = tid & 31;
    const int brow = blockIdx.y, bcol = blockIdx.x;

    const int part = (tid >> 2) & 1;
    const __nv_bfloat16* srcA = (part ? Al : Ah) + (size_t)(brow * 128) * 1024;
    const __nv_bfloat16* srcB = (part ? Bl : Bh) + (size_t)(bcol * 128) * 1024;

    GemmCore core;
    core.run(sbase, smem, srcA, srcB, tid, wid, lane);
    core.epilogue(C, mask, op, brow, bcol, wid, lane);
}

// ---------------------------------------------------------------------------
// Mask normalization (dtype-agnostic) -> uint8 0/1
// ---------------------------------------------------------------------------
__global__ __launch_bounds__(256) void mask_convert_kernel(const unsigned char* __restrict__ mraw)
{
    __shared__ int s_float, s_odd;
    if (threadIdx.x == 0) { s_float = 0; s_odd = 0; }
    __syncthreads();
    for (int i = threadIdx.x; i < 4096; i += 256) {
        unsigned char v = mraw[i];
        if (v == 0x3F) s_float = 1;
        if (v != 0 && (i & 3) != 0) s_odd = 1;
    }
    __syncthreads();
    const int dtype = s_float ? 2 : (s_odd ? 0 : 1);

    const int m0 = blockIdx.x * 256 + threadIdx.x;
    for (int m = m0; m < BT; m += 64 * 256) {
        unsigned char r;
        if (dtype == 0)      r = (mraw[m] != 0);
        else if (dtype == 1) r = (((const int*)mraw)[m] != 0);
        else                 r = (((const float*)mraw)[m] != 0.0f);
        g_mask[m] = r;
    }
}

// ---------------------------------------------------------------------------
// kv partial, register-blocked 4d x 16e per thread. grid (BH, 8).
// ---------------------------------------------------------------------------
__global__ __launch_bounds__(256) void kv_partial_kernel()
{
    const int tid = threadIdx.x;
    const int bh = blockIdx.x, sy = blockIdx.y;
    const int b = bh >> 4, h = bh & 15;
    const int t0 = sy * 512;

    __shared__ __align__(16) float Ks[2][32][64];
    __shared__ __align__(16) float Vs[2][32][64];
    const uint32_t sK = smem_u32(&Ks[0][0][0]);
    const uint32_t sV = smem_u32(&Vs[0][0][0]);

    const int q  = tid >> 6;
    const int r  = tid & 63;
    const int d0 = (r >> 2) * 4;
    const int e0 = (r & 3) * 16;

    float acc[4][16];
#pragma unroll
    for (int j = 0; j < 4; j++)
#pragma unroll
        for (int i = 0; i < 16; i++) acc[j][i] = 0.f;
    float ks[4] = {0.f, 0.f, 0.f, 0.f};

    const size_t base = ((size_t)b * Tc) * Dc + h * 64;

    const int tl0 = tid >> 4,         c40 = (tid & 15) * 4;
    const int tl1 = (tid + 256) >> 4, c41 = ((tid + 256) & 15) * 4;
    const uint32_t so0 = (uint32_t)((tl0 * 64 + c40) * 4);
    const uint32_t so1 = (uint32_t)((tl1 * 64 + c41) * 4);

    auto load_chunk = [&](int c, int bufsel) {
        uint32_t kb = sK + bufsel * 8192, vb = sV + bufsel * 8192;
        size_t g0 = base + (size_t)(t0 + c * 32 + tl0) * Dc + c40;
        size_t g1 = base + (size_t)(t0 + c * 32 + tl1) * Dc + c41;
        cp16(kb + so0, g_k + g0);
        cp16(vb + so0, g_v + g0);
        cp16(kb + so1, g_k + g1);
        cp16(vb + so1, g_v + g1);
    };

    load_chunk(0, 0);
    CP_COMMIT();

#pragma unroll 1
    for (int c = 0; c < 16; c++) {
        if (c < 15) {
            load_chunk(c + 1, (c + 1) & 1);
            CP_COMMIT();
            CP_WAIT1();
        } else {
            CP_WAIT0();
        }
        __syncthreads();
        const int cb = c & 1;
#pragma unroll
        for (int tt = 0; tt < 8; tt++) {
            const int t = q * 8 + tt;
            float4 kd = *(const float4*)&Ks[cb][t][d0];
            float4 v0 = *(const float4*)&Vs[cb][t][e0];
            float4 v1 = *(const float4*)&Vs[cb][t][e0 + 4];
            float4 v2 = *(const float4*)&Vs[cb][t][e0 + 8];
            float4 v3 = *(const float4*)&Vs[cb][t][e0 + 12];
            ks[0] += kd.x; ks[1] += kd.y; ks[2] += kd.z; ks[3] += kd.w;
            const float kv4[4] = {kd.x, kd.y, kd.z, kd.w};
            const float vv[16] = {v0.x, v0.y, v0.z, v0.w, v1.x, v1.y, v1.z, v1.w,
                                  v2.x, v2.y, v2.z, v2.w, v3.x, v3.y, v3.z, v3.w};
#pragma unroll
            for (int j = 0; j < 4; j++)
#pragma unroll
                for (int i = 0; i < 16; i++)
                    acc[j][i] = fmaf(kv4[j], vv[i], acc[j][i]);
        }
        __syncthreads();
    }

    const int slot = bh * SPLIT + sy * 4 + q;
    float* outp = g_kvp + (size_t)slot * 4096;
#pragma unroll
    for (int j = 0; j < 4; j++) {
        float* rp = outp + (d0 + j) * 64 + e0;
        *(float4*)(rp + 0)  = make_float4(acc[j][0], acc[j][1], acc[j][2], acc[j][3]);
        *(float4*)(rp + 4)  = make_float4(acc[j][4], acc[j][5], acc[j][6], acc[j][7]);
        *(float4*)(rp + 8)  = make_float4(acc[j][8], acc[j][9], acc[j][10], acc[j][11]);
        *(float4*)(rp + 12) = make_float4(acc[j][12], acc[j][13], acc[j][14], acc[j][15]);
    }
    if ((r & 3) == 0) {
#pragma unroll
        for (int j = 0; j < 4; j++)
            g_ksp[slot * 64 + d0 + j] = ks[j];
    }
}

// ---------------------------------------------------------------------------
__global__ __launch_bounds__(256) void kv_reduce_kernel()
{
    const int bh = blockIdx.x, tid = threadIdx.x;
#pragma unroll
    for (int j = 0; j < 4; j++) {
        int off = tid * 16 + j * 4;
        float4 s = make_float4(0.f, 0.f, 0.f, 0.f);
#pragma unroll
        for (int sp = 0; sp < SPLIT; sp++) {
            float4 p = *(const float4*)(g_kvp + ((size_t)(bh * SPLIT + sp)) * 4096 + off);
            s.x += p.x; s.y += p.y; s.z += p.z; s.w += p.w;
        }
        *(float4*)(g_kv + (size_t)bh * 4096 + off) = s;
    }
    if (tid < 64) {
        float s = 0.f;
#pragma unroll
        for (int sp = 0; sp < SPLIT; sp++)
            s += g_ksp[(bh * SPLIT + sp) * 64 + tid];
        g_ksum[bh * 64 + tid] = s;
    }
}

// ---------------------------------------------------------------------------
// attn out, register-blocked 4 t-rows x 16 e-cols; writes bf16 hi/lo split.
// ---------------------------------------------------------------------------
constexpr int QS_STRIDE = 260;

__global__ __launch_bounds__(256) void attn_out_kernel()
{
    const int tid = threadIdx.x;
    const int bh = blockIdx.y;
    const int b = bh >> 4, h = bh & 15;
    const int t0 = blockIdx.x * 256;

    __shared__ __align__(16) float KV[4096];
    __shared__ __align__(16) float Qs[16][QS_STRIDE];
    __shared__ float Ksm[64];

#pragma unroll
    for (int j = 0; j < 4; j++) {
        int f = tid + j * 256;
        *(float4*)&KV[f * 4] = *(const float4*)(g_kv + (size_t)bh * 4096 + f * 4);
    }
    if (tid < 64) Ksm[tid] = g_ksum[bh * 64 + tid];

    const size_t base = ((size_t)b * Tc) * Dc + h * 64;
    const int tl4 = tid >> 2;
    const int e0 = (tid & 3) * 16;

    float acc[4][16];
#pragma unroll
    for (int j = 0; j < 4; j++)
#pragma unroll
        for (int i = 0; i < 16; i++) acc[j][i] = 0.f;
    float nrm[4] = {0.f, 0.f, 0.f, 0.f};

#pragma unroll 1
    for (int dc = 0; dc < 4; dc++) {
        __syncthreads();
#pragma unroll
        for (int j = 0; j < 16; j++) {
            int idx = tid + j * 256;
            int d = idx & 15, t = idx >> 4;
            Qs[d][t] = g_q[base + (size_t)(t0 + t) * Dc + dc * 16 + d];
        }
        __syncthreads();
#pragma unroll
        for (int d2 = 0; d2 < 16; d2++) {
            const int dg = dc * 16 + d2;
            float4 qv = *(const float4*)&Qs[d2][tl4 * 4];
            const float km = Ksm[dg];
            const float4* kvp = (const float4*)&KV[dg * 64 + e0];
            float4 w0 = kvp[0], w1 = kvp[1], w2 = kvp[2], w3 = kvp[3];
            const float qq[4] = {qv.x, qv.y, qv.z, qv.w};
            const float vv[16] = {w0.x, w0.y, w0.z, w0.w, w1.x, w1.y, w1.z, w1.w,
                                  w2.x, w2.y, w2.z, w2.w, w3.x, w3.y, w3.z, w3.w};
#pragma unroll
            for (int j = 0; j < 4; j++) {
                nrm[j] = fmaf(qq[j], km, nrm[j]);
#pragma unroll
                for (int i = 0; i < 16; i++)
                    acc[j][i] = fmaf(qq[j], vv[i], acc[j][i]);
            }
        }
    }

#pragma unroll
    for (int j = 0; j < 4; j++) {
        const float inv = 1.f / fmaxf(nrm[j], 1e-6f);
        const size_t idx = base + (size_t)(t0 + tl4 * 4 + j) * Dc + e0;
#pragma unroll
        for (int g = 0; g < 4; g++) {
            float a0 = acc[j][g * 4 + 0] * inv, a1 = acc[j][g * 4 + 1] * inv;
            float a2 = acc[j][g * 4 + 2] * inv, a3 = acc[j][g * 4 + 3] * inv;
            float h0 = __bfloat162float(__float2bfloat16(a0));
            float h1 = __bfloat162float(__float2bfloat16(a1));
            float h2 = __bfloat162float(__float2bfloat16(a2));
            float h3 = __bfloat162float(__float2bfloat16(a3));
            *(uint2*)(g_ah + idx + g * 4) = make_uint2(pack_bf2(a0, a1), pack_bf2(a2, a3));
            *(uint2*)(g_al + idx + g * 4) = make_uint2(pack_bf2(a0 - h0, a1 - h1),
                                                       pack_bf2(a2 - h2, a3 - h3));
        }
    }
}

// ---------------------------------------------------------------------------
extern "C" void kernel_launch(void* const* d_in, const int* in_sizes, int n_in,
                              void* d_out, int out_size)
{
    const float* x          = (const float*)d_in[0];
    const unsigned char* mk = (const unsigned char*)d_in[1];
    float* out              = (float*)d_out;

    float *qp, *kp, *vp;
    unsigned char* mkc;
    __nv_bfloat16 *xh, *xl, *ah, *al, *wh, *wl;
    cudaGetSymbolAddress((void**)&qp, g_q);
    cudaGetSymbolAddress((void**)&kp, g_k);
    cudaGetSymbolAddress((void**)&vp, g_v);
    cudaGetSymbolAddress((void**)&mkc, g_mask);
    cudaGetSymbolAddress((void**)&xh, g_xh);
    cudaGetSymbolAddress((void**)&xl, g_xl);
    cudaGetSymbolAddress((void**)&ah, g_ah);
    cudaGetSymbolAddress((void**)&al, g_al);
    cudaGetSymbolAddress((void**)&wh, g_wh);
    cudaGetSymbolAddress((void**)&wl, g_wl);

    cudaFuncSetAttribute(gemm_qkv_kernel,
                         cudaFuncAttributeMaxDynamicSharedMemorySize, GSM_TOTAL);
    cudaFuncSetAttribute(gemm_tc_kernel,
                         cudaFuncAttributeMaxDynamicSharedMemorySize, GSM_TOTAL);

    const int n4x = BT * Dc / 4;
    // Launch order: 5 cheap prep launches so ncu (-s 5 -c 1) profiles the fused GEMM (6th).
    split_kernel<<<2048, 256>>>((const float4*)x, (uint2*)xh, (uint2*)xl, 0, n4x / 2);       // 1
    split_kernel<<<2048, 256>>>((const float4*)x, (uint2*)xh, (uint2*)xl, n4x / 2, n4x);     // 2
    splitw_kernel<<<dim3(512, 2), 256>>>((const float4*)d_in[2], (const float4*)d_in[3], 0); // 3
    splitw_kernel<<<dim3(512, 2), 256>>>((const float4*)d_in[4], (const float4*)d_in[5], 2); // 4
    mask_convert_kernel<<<64, 256>>>(mk);                                                    // 5

    gemm_qkv_kernel<<<dim3(24, 128), 256, GSM_TOTAL>>>(xh, xl, qp, kp, vp, mkc);             // 6 <- profiled
    kv_partial_kernel<<<dim3(BH, 8), 256>>>();
    kv_reduce_kernel<<<BH, 256>>>();
    attn_out_kernel<<<dim3(Tc / 256, BH), 256>>>();
    gemm_tc_kernel<<<dim3(8, 128), 256, GSM_TOTAL>>>(ah, al, wh + 3 * (size_t)Dc * Dc, wl + 3 * (size_t)Dc * Dc, out, mkc, 0);
}

// round 13
// speedup vs baseline: 1.2350x; 1.0072x over previous
#include <cuda_runtime.h>
#include <cuda_bf16.h>
#include <math.h>
#include <stdint.h>

// Problem constants
constexpr int Bc = 4, Tc = 4096, Dc = 1024, Hc = 16, HDc = 64;
constexpr int BT = Bc * Tc;          // 16384 rows
constexpr int BH = Bc * Hc;          // 64 (b,h) pairs
constexpr int SPLIT = 32;            // total kv partial slots (8 blocks x 4 groups)

// Scratch (device globals: no allocation allowed in kernel_launch)
__device__ float g_q[BT * Dc];
__device__ float g_k[BT * Dc];
__device__ float g_v[BT * Dc];
__device__ float g_kvp[BH * SPLIT * HDc * HDc];
__device__ float g_ksp[BH * SPLIT * HDc];
__device__ float g_kv[BH * HDc * HDc];
__device__ float g_ksum[BH * HDc];
__device__ unsigned char g_mask[BT];
// bf16 hi/lo split operand buffers
__device__ __nv_bfloat16 g_xh[BT * Dc], g_xl[BT * Dc];
__device__ __nv_bfloat16 g_ah[BT * Dc], g_al[BT * Dc];
__device__ __nv_bfloat16 g_wh[4][Dc * Dc], g_wl[4][Dc * Dc];

__device__ __forceinline__ float phi(float x) {
    return x > 0.f ? x + 1.f : expf(x);
}

__device__ __forceinline__ uint32_t smem_u32(const void* p) {
    uint32_t a;
    asm("{ .reg .u64 t; cvta.to.shared.u64 t, %1; cvt.u32.u64 %0, t; }" : "=r"(a) : "l"(p));
    return a;
}

__device__ __forceinline__ uint32_t pack_bf2(float x, float y) {
    __nv_bfloat162 h = __floats2bfloat162_rn(x, y);
    return *(uint32_t*)&h;
}

__device__ __forceinline__ void cp16(uint32_t dst, const void* src) {
    asm volatile("cp.async.cg.shared.global [%0], [%1], 16;" :: "r"(dst), "l"(src));
}
#define CP_COMMIT() asm volatile("cp.async.commit_group;" ::: "memory")
#define CP_WAIT1()  asm volatile("cp.async.wait_group 1;" ::: "memory")
#define CP_WAIT0()  asm volatile("cp.async.wait_group 0;" ::: "memory")

// ---------------------------------------------------------------------------
// fp32 -> (hi, lo) bf16 split, vectorized
// ---------------------------------------------------------------------------
__global__ __launch_bounds__(256) void split_kernel(
    const float4* __restrict__ src, uint2* __restrict__ hi, uint2* __restrict__ lo,
    int i0, int n4)
{
    for (int i = i0 + blockIdx.x * 256 + threadIdx.x; i < n4; i += gridDim.x * 256) {
        float4 v = src[i];
        float hx = __bfloat162float(__float2bfloat16(v.x));
        float hy = __bfloat162float(__float2bfloat16(v.y));
        float hz = __bfloat162float(__float2bfloat16(v.z));
        float hw = __bfloat162float(__float2bfloat16(v.w));
        hi[i] = make_uint2(pack_bf2(v.x, v.y), pack_bf2(v.z, v.w));
        lo[i] = make_uint2(pack_bf2(v.x - hx, v.y - hy), pack_bf2(v.z - hz, v.w - hw));
    }
}

// two weight matrices per launch (blockIdx.y = which of the pair)
__global__ __launch_bounds__(256) void splitw_kernel(
    const float4* __restrict__ wa, const float4* __restrict__ wb, int wbase)
{
    const int wsel = wbase + blockIdx.y;
    const float4* src = blockIdx.y == 0 ? wa : wb;
    uint2* hi = (uint2*)(g_wh[wsel]);
    uint2* lo = (uint2*)(g_wl[wsel]);
    const int n4 = Dc * Dc / 4;
    for (int i = blockIdx.x * 256 + threadIdx.x; i < n4; i += gridDim.x * 256) {
        float4 v = src[i];
        float hx = __bfloat162float(__float2bfloat16(v.x));
        float hy = __bfloat162float(__float2bfloat16(v.y));
        float hz = __bfloat162float(__float2bfloat16(v.z));
        float hw = __bfloat162float(__float2bfloat16(v.w));
        hi[i] = make_uint2(pack_bf2(v.x, v.y), pack_bf2(v.z, v.w));
        lo[i] = make_uint2(pack_bf2(v.x - hx, v.y - hy), pack_bf2(v.z - hz, v.w - hw));
    }
}

// ---------------------------------------------------------------------------
// 3-term bf16-split tensor-core GEMM mainloop (shared).
// Tile 128x128, 8 warps (4m x 2n), warp tile 32x64, cp.async 3-stage, 2 CTA/SM.
// ---------------------------------------------------------------------------
constexpr int GSM_STAGE = 32768;
constexpr int NSTAGES = 3;
constexpr int GSM_TOTAL = NSTAGES * GSM_STAGE;   // 96KB -> 2 CTAs/SM

struct GemmCore {
    float acc[2][8][4];

    __device__ __forceinline__ void run(
        uint32_t sbase, char* smem,
        const __nv_bfloat16* srcA, const __nv_bfloat16* srcB,
        int tid, int wid, int lane)
    {
        const int wm = wid & 3, wn = wid >> 2;
        const int r0 = tid >> 3;
        const int part = (tid >> 2) & 1;
        const int ci = tid & 3;
        uint32_t dstA[4];
#pragma unroll
        for (int i = 0; i < 4; i++) {
            int row = r0 + 32 * i;
            dstA[i] = ((uint32_t)(row * 128 + part * 64 + ci * 16)) ^ (uint32_t)((row & 7) << 4);
        }

        auto load_stage = [&](int s, int buf) {
            uint32_t sb = sbase + buf * GSM_STAGE;
            const int koff = s * 32 + ci * 8;
#pragma unroll
            for (int i = 0; i < 4; i++) {
                int row = r0 + 32 * i;
                cp16(sb + dstA[i], srcA + (size_t)row * 1024 + koff);
                cp16(sb + 16384 + dstA[i], srcB + (size_t)row * 1024 + koff);
            }
        };

#pragma unroll
        for (int s = 0; s < NSTAGES - 1; s++) {
            load_stage(s, s);
            CP_COMMIT();
        }

#pragma unroll
        for (int mt = 0; mt < 2; mt++)
#pragma unroll
            for (int nt = 0; nt < 8; nt++)
#pragma unroll
                for (int j = 0; j < 4; j++) acc[mt][nt][j] = 0.f;

        const int lrow = lane & 7;
        const int seg = lane >> 3;
        const int segr = (seg & 1) << 3;
        const int segc = (seg & 2) << 3;

        const uint32_t swl = (uint32_t)(lrow << 4);
        uint32_t rowA[2], rowB[4], cxH[2], cxL[2];
#pragma unroll
        for (int mt = 0; mt < 2; mt++)
            rowA[mt] = (uint32_t)((wm * 32 + mt * 16 + lrow + segr) * 128);
#pragma unroll
        for (int n = 0; n < 4; n++)
            rowB[n] = (uint32_t)((wn * 64 + n * 16 + lrow + segr) * 128);
#pragma unroll
        for (int ks2 = 0; ks2 < 2; ks2++) {
            cxH[ks2] = ((uint32_t)(ks2 * 32 + segc)) ^ swl;
            cxL[ks2] = ((uint32_t)(64 + ks2 * 32 + segc)) ^ swl;
        }

        constexpr int NT = 32;
        int buf = 0;
#pragma unroll 1
        for (int t = 0; t < NT; t++) {
            CP_WAIT1();
            __syncthreads();
            if (t + NSTAGES - 1 < NT) {
                int lb = buf + NSTAGES - 1; if (lb >= NSTAGES) lb -= NSTAGES;
                load_stage(t + NSTAGES - 1, lb);
            }
            CP_COMMIT();

            const uint32_t sA = sbase + buf * GSM_STAGE;
            const uint32_t sB = sA + 16384;
            if (++buf == NSTAGES) buf = 0;

#pragma unroll
            for (int ks2 = 0; ks2 < 2; ks2++) {
                uint32_t afrH[2][4], afrL[2][4];
#pragma unroll
                for (int mt = 0; mt < 2; mt++) {
                    asm volatile("ldmatrix.sync.aligned.m8n8.x4.shared.b16 {%0,%1,%2,%3}, [%4];"
                        : "=r"(afrH[mt][0]), "=r"(afrH[mt][1]), "=r"(afrH[mt][2]), "=r"(afrH[mt][3])
                        : "r"(sA + rowA[mt] + cxH[ks2]));
                    asm volatile("ldmatrix.sync.aligned.m8n8.x4.shared.b16 {%0,%1,%2,%3}, [%4];"
                        : "=r"(afrL[mt][0]), "=r"(afrL[mt][1]), "=r"(afrL[mt][2]), "=r"(afrL[mt][3])
                        : "r"(sA + rowA[mt] + cxL[ks2]));
                }
                uint32_t bfrH[4][4], bfrL[4][4];
#pragma unroll
                for (int nt2 = 0; nt2 < 4; nt2++) {
                    asm volatile("ldmatrix.sync.aligned.m8n8.x4.shared.b16 {%0,%1,%2,%3}, [%4];"
                        : "=r"(bfrH[nt2][0]), "=r"(bfrH[nt2][1]), "=r"(bfrH[nt2][2]), "=r"(bfrH[nt2][3])
                        : "r"(sB + rowB[nt2] + cxH[ks2]));
                    asm volatile("ldmatrix.sync.aligned.m8n8.x4.shared.b16 {%0,%1,%2,%3}, [%4];"
                        : "=r"(bfrL[nt2][0]), "=r"(bfrL[nt2][1]), "=r"(bfrL[nt2][2]), "=r"(bfrL[nt2][3])
                        : "r"(sB + rowB[nt2] + cxL[ks2]));
                }

#pragma unroll
                for (int mt = 0; mt < 2; mt++)
#pragma unroll
                    for (int nt = 0; nt < 8; nt++) {
                        const int g = nt >> 1, h = nt & 1;
                        asm volatile(
                            "mma.sync.aligned.m16n8k16.row.col.f32.bf16.bf16.f32 "
                            "{%0,%1,%2,%3}, {%4,%5,%6,%7}, {%8,%9}, {%0,%1,%2,%3};"
                            : "+f"(acc[mt][nt][0]), "+f"(acc[mt][nt][1]),
                              "+f"(acc[mt][nt][2]), "+f"(acc[mt][nt][3])
                            : "r"(afrH[mt][0]), "r"(afrH[mt][1]), "r"(afrH[mt][2]), "r"(afrH[mt][3]),
                              "r"(bfrH[g][h]), "r"(bfrH[g][h + 2]));
                        asm volatile(
                            "mma.sync.aligned.m16n8k16.row.col.f32.bf16.bf16.f32 "
                            "{%0,%1,%2,%3}, {%4,%5,%6,%7}, {%8,%9}, {%0,%1,%2,%3};"
                            : "+f"(acc[mt][nt][0]), "+f"(acc[mt][nt][1]),
                              "+f"(acc[mt][nt][2]), "+f"(acc[mt][nt][3])
                            : "r"(afrL[mt][0]), "r"(afrL[mt][1]), "r"(afrL[mt][2]), "r"(afrL[mt][3]),
                              "r"(bfrH[g][h]), "r"(bfrH[g][h + 2]));
                        asm volatile(
                            "mma.sync.aligned.m16n8k16.row.col.f32.bf16.bf16.f32 "
                            "{%0,%1,%2,%3}, {%4,%5,%6,%7}, {%8,%9}, {%0,%1,%2,%3};"
                            : "+f"(acc[mt][nt][0]), "+f"(acc[mt][nt][1]),
                              "+f"(acc[mt][nt][2]), "+f"(acc[mt][nt][3])
                            : "r"(afrH[mt][0]), "r"(afrH[mt][1]), "r"(afrH[mt][2]), "r"(afrH[mt][3]),
                              "r"(bfrL[g][h]), "r"(bfrL[g][h + 2]));
                    }
            }
        }
    }

    __device__ __forceinline__ void epilogue(
        float* C, const unsigned char* mask, int op,
        int brow, int bcol, int wid, int lane)
    {
        const int wm = wid & 3, wn = wid >> 2;
        const int r0e = brow * 128 + wm * 32 + (lane >> 2);
        const int c0 = bcol * 128 + wn * 64 + (lane & 3) * 2;
        const bool do_phi = (op == 1 || op == 2);
        const bool do_msk = (op >= 2);
#pragma unroll
        for (int mt = 0; mt < 2; mt++) {
            const int r = r0e + mt * 16;
            const bool mz0 = do_msk && (mask[r] != 0);
            const bool mz1 = do_msk && (mask[r + 8] != 0);
#pragma unroll
            for (int nt = 0; nt < 8; nt++) {
                float2 v0 = make_float2(acc[mt][nt][0], acc[mt][nt][1]);
                float2 v1 = make_float2(acc[mt][nt][2], acc[mt][nt][3]);
                if (do_phi) {
                    v0.x = phi(v0.x); v0.y = phi(v0.y);
                    v1.x = phi(v1.x); v1.y = phi(v1.y);
                }
                if (mz0) { v0.x = 0.f; v0.y = 0.f; }
                if (mz1) { v1.x = 0.f; v1.y = 0.f; }
                *(float2*)(C + (size_t)r * 1024 + c0 + nt * 8) = v0;
                *(float2*)(C + (size_t)(r + 8) * 1024 + c0 + nt * 8) = v1;
            }
        }
    }
};

// Fused K/V GEMM: grid (16, 128). blockIdx.x>>3 selects K (W1, op2) / V (W2, op3).
__global__ __launch_bounds__(256, 2) void gemm_kv_kernel(
    const __nv_bfloat16* __restrict__ Ah, const __nv_bfloat16* __restrict__ Al,
    float* __restrict__ C1, float* __restrict__ C2,
    const unsigned char* __restrict__ mask)
{
    extern __shared__ __align__(1024) char smem[];
    const uint32_t sbase = smem_u32(smem);
    const int tid = threadIdx.x;
    const int wid = tid >> 5, lane = tid & 31;
    const int brow = blockIdx.y;
    const int sel = blockIdx.x >> 3;         // 0=K, 1=V
    const int bcol = blockIdx.x & 7;

    const int part = (tid >> 2) & 1;
    const __nv_bfloat16* srcA = (part ? Al : Ah) + (size_t)(brow * 128) * 1024;
    const __nv_bfloat16* srcB = (part ? g_wl[sel + 1] : g_wh[sel + 1]) + (size_t)(bcol * 128) * 1024;

    GemmCore core;
    core.run(sbase, smem, srcA, srcB, tid, wid, lane);

    float* C = sel == 0 ? C1 : C2;
    core.epilogue(C, mask, sel + 2, brow, bcol, wid, lane);
}

// Plain GEMM (Q projection op=1, Wo projection op=0).
__global__ __launch_bounds__(256, 2) void gemm_tc_kernel(
    const __nv_bfloat16* __restrict__ Ah, const __nv_bfloat16* __restrict__ Al,
    const __nv_bfloat16* __restrict__ Bh, const __nv_bfloat16* __restrict__ Bl,
    float* __restrict__ C, const unsigned char* __restrict__ mask, int op)
{
    extern __shared__ __align__(1024) char smem[];
    const uint32_t sbase = smem_u32(smem);
    const int tid = threadIdx.x;
    const int wid = tid >> 5, lane = tid & 31;
    const int brow = blockIdx.y, bcol = blockIdx.x;

    const int part = (tid >> 2) & 1;
    const __nv_bfloat16* srcA = (part ? Al : Ah) + (size_t)(brow * 128) * 1024;
    const __nv_bfloat16* srcB = (part ? Bl : Bh) + (size_t)(bcol * 128) * 1024;

    GemmCore core;
    core.run(sbase, smem, srcA, srcB, tid, wid, lane);
    core.epilogue(C, mask, op, brow, bcol, wid, lane);
}

// ---------------------------------------------------------------------------
// Mask normalization (dtype-agnostic) -> uint8 0/1
// ---------------------------------------------------------------------------
__global__ __launch_bounds__(256) void mask_convert_kernel(const unsigned char* __restrict__ mraw)
{
    __shared__ int s_float, s_odd;
    if (threadIdx.x == 0) { s_float = 0; s_odd = 0; }
    __syncthreads();
    for (int i = threadIdx.x; i < 4096; i += 256) {
        unsigned char v = mraw[i];
        if (v == 0x3F) s_float = 1;
        if (v != 0 && (i & 3) != 0) s_odd = 1;
    }
    __syncthreads();
    const int dtype = s_float ? 2 : (s_odd ? 0 : 1);

    const int m0 = blockIdx.x * 256 + threadIdx.x;
    for (int m = m0; m < BT; m += 64 * 256) {
        unsigned char r;
        if (dtype == 0)      r = (mraw[m] != 0);
        else if (dtype == 1) r = (((const int*)mraw)[m] != 0);
        else                 r = (((const float*)mraw)[m] != 0.0f);
        g_mask[m] = r;
    }
}

// ---------------------------------------------------------------------------
// kv partial, register-blocked 4d x 16e per thread. grid (BH, 8).
// ---------------------------------------------------------------------------
__global__ __launch_bounds__(256) void kv_partial_kernel()
{
    const int tid = threadIdx.x;
    const int bh = blockIdx.x, sy = blockIdx.y;
    const int b = bh >> 4, h = bh & 15;
    const int t0 = sy * 512;

    __shared__ __align__(16) float Ks[2][32][64];
    __shared__ __align__(16) float Vs[2][32][64];
    const uint32_t sK = smem_u32(&Ks[0][0][0]);
    const uint32_t sV = smem_u32(&Vs[0][0][0]);

    const int q  = tid >> 6;
    const int r  = tid & 63;
    const int d0 = (r >> 2) * 4;
    const int e0 = (r & 3) * 16;

    float acc[4][16];
#pragma unroll
    for (int j = 0; j < 4; j++)
#pragma unroll
        for (int i = 0; i < 16; i++) acc[j][i] = 0.f;
    float ks[4] = {0.f, 0.f, 0.f, 0.f};

    const size_t base = ((size_t)b * Tc) * Dc + h * 64;

    const int tl0 = tid >> 4,         c40 = (tid & 15) * 4;
    const int tl1 = (tid + 256) >> 4, c41 = ((tid + 256) & 15) * 4;
    const uint32_t so0 = (uint32_t)((tl0 * 64 + c40) * 4);
    const uint32_t so1 = (uint32_t)((tl1 * 64 + c41) * 4);

    auto load_chunk = [&](int c, int bufsel) {
        uint32_t kb = sK + bufsel * 8192, vb = sV + bufsel * 8192;
        size_t g0 = base + (size_t)(t0 + c * 32 + tl0) * Dc + c40;
        size_t g1 = base + (size_t)(t0 + c * 32 + tl1) * Dc + c41;
        cp16(kb + so0, g_k + g0);
        cp16(vb + so0, g_v + g0);
        cp16(kb + so1, g_k + g1);
        cp16(vb + so1, g_v + g1);
    };

    load_chunk(0, 0);
    CP_COMMIT();

#pragma unroll 1
    for (int c = 0; c < 16; c++) {
        if (c < 15) {
            load_chunk(c + 1, (c + 1) & 1);
            CP_COMMIT();
            CP_WAIT1();
        } else {
            CP_WAIT0();
        }
        __syncthreads();
        const int cb = c & 1;
#pragma unroll
        for (int tt = 0; tt < 8; tt++) {
            const int t = q * 8 + tt;
            float4 kd = *(const float4*)&Ks[cb][t][d0];
            float4 v0 = *(const float4*)&Vs[cb][t][e0];
            float4 v1 = *(const float4*)&Vs[cb][t][e0 + 4];
            float4 v2 = *(const float4*)&Vs[cb][t][e0 + 8];
            float4 v3 = *(const float4*)&Vs[cb][t][e0 + 12];
            ks[0] += kd.x; ks[1] += kd.y; ks[2] += kd.z; ks[3] += kd.w;
            const float kv4[4] = {kd.x, kd.y, kd.z, kd.w};
            const float vv[16] = {v0.x, v0.y, v0.z, v0.w, v1.x, v1.y, v1.z, v1.w,
                                  v2.x, v2.y, v2.z, v2.w, v3.x, v3.y, v3.z, v3.w};
#pragma unroll
            for (int j = 0; j < 4; j++)
#pragma unroll
                for (int i = 0; i < 16; i++)
                    acc[j][i] = fmaf(kv4[j], vv[i], acc[j][i]);
        }
        __syncthreads();
    }

    const int slot = bh * SPLIT + sy * 4 + q;
    float* outp = g_kvp + (size_t)slot * 4096;
#pragma unroll
    for (int j = 0; j < 4; j++) {
        float* rp = outp + (d0 + j) * 64 + e0;
        *(float4*)(rp + 0)  = make_float4(acc[j][0], acc[j][1], acc[j][2], acc[j][3]);
        *(float4*)(rp + 4)  = make_float4(acc[j][4], acc[j][5], acc[j][6], acc[j][7]);
        *(float4*)(rp + 8)  = make_float4(acc[j][8], acc[j][9], acc[j][10], acc[j][11]);
        *(float4*)(rp + 12) = make_float4(acc[j][12], acc[j][13], acc[j][14], acc[j][15]);
    }
    if ((r & 3) == 0) {
#pragma unroll
        for (int j = 0; j < 4; j++)
            g_ksp[slot * 64 + d0 + j] = ks[j];
    }
}

// ---------------------------------------------------------------------------
__global__ __launch_bounds__(256) void kv_reduce_kernel()
{
    const int bh = blockIdx.x, tid = threadIdx.x;
#pragma unroll
    for (int j = 0; j < 4; j++) {
        int off = tid * 16 + j * 4;
        float4 s = make_float4(0.f, 0.f, 0.f, 0.f);
#pragma unroll
        for (int sp = 0; sp < SPLIT; sp++) {
            float4 p = *(const float4*)(g_kvp + ((size_t)(bh * SPLIT + sp)) * 4096 + off);
            s.x += p.x; s.y += p.y; s.z += p.z; s.w += p.w;
        }
        *(float4*)(g_kv + (size_t)bh * 4096 + off) = s;
    }
    if (tid < 64) {
        float s = 0.f;
#pragma unroll
        for (int sp = 0; sp < SPLIT; sp++)
            s += g_ksp[(bh * SPLIT + sp) * 64 + tid];
        g_ksum[bh * 64 + tid] = s;
    }
}

// ---------------------------------------------------------------------------
// attn out, register-blocked 4 t-rows x 16 e-cols; writes bf16 hi/lo split.
// ---------------------------------------------------------------------------
constexpr int QS_STRIDE = 260;

__global__ __launch_bounds__(256) void attn_out_kernel()
{
    const int tid = threadIdx.x;
    const int bh = blockIdx.y;
    const int b = bh >> 4, h = bh & 15;
    const int t0 = blockIdx.x * 256;

    __shared__ __align__(16) float KV[4096];
    __shared__ __align__(16) float Qs[16][QS_STRIDE];
    __shared__ float Ksm[64];

#pragma unroll
    for (int j = 0; j < 4; j++) {
        int f = tid + j * 256;
        *(float4*)&KV[f * 4] = *(const float4*)(g_kv + (size_t)bh * 4096 + f * 4);
    }
    if (tid < 64) Ksm[tid] = g_ksum[bh * 64 + tid];

    const size_t base = ((size_t)b * Tc) * Dc + h * 64;
    const int tl4 = tid >> 2;
    const int e0 = (tid & 3) * 16;

    float acc[4][16];
#pragma unroll
    for (int j = 0; j < 4; j++)
#pragma unroll
        for (int i = 0; i < 16; i++) acc[j][i] = 0.f;
    float nrm[4] = {0.f, 0.f, 0.f, 0.f};

#pragma unroll 1
    for (int dc = 0; dc < 4; dc++) {
        __syncthreads();
#pragma unroll
        for (int j = 0; j < 16; j++) {
            int idx = tid + j * 256;
            int d = idx & 15, t = idx >> 4;
            Qs[d][t] = g_q[base + (size_t)(t0 + t) * Dc + dc * 16 + d];
        }
        __syncthreads();
#pragma unroll
        for (int d2 = 0; d2 < 16; d2++) {
            const int dg = dc * 16 + d2;
            float4 qv = *(const float4*)&Qs[d2][tl4 * 4];
            const float km = Ksm[dg];
            const float4* kvp = (const float4*)&KV[dg * 64 + e0];
            float4 w0 = kvp[0], w1 = kvp[1], w2 = kvp[2], w3 = kvp[3];
            const float qq[4] = {qv.x, qv.y, qv.z, qv.w};
            const float vv[16] = {w0.x, w0.y, w0.z, w0.w, w1.x, w1.y, w1.z, w1.w,
                                  w2.x, w2.y, w2.z, w2.w, w3.x, w3.y, w3.z, w3.w};
#pragma unroll
            for (int j = 0; j < 4; j++) {
                nrm[j] = fmaf(qq[j], km, nrm[j]);
#pragma unroll
                for (int i = 0; i < 16; i++)
                    acc[j][i] = fmaf(qq[j], vv[i], acc[j][i]);
            }
        }
    }

#pragma unroll
    for (int j = 0; j < 4; j++) {
        const float inv = 1.f / fmaxf(nrm[j], 1e-6f);
        const size_t idx = base + (size_t)(t0 + tl4 * 4 + j) * Dc + e0;
#pragma unroll
        for (int g = 0; g < 4; g++) {
            float a0 = acc[j][g * 4 + 0] * inv, a1 = acc[j][g * 4 + 1] * inv;
            float a2 = acc[j][g * 4 + 2] * inv, a3 = acc[j][g * 4 + 3] * inv;
            float h0 = __bfloat162float(__float2bfloat16(a0));
            float h1 = __bfloat162float(__float2bfloat16(a1));
            float h2 = __bfloat162float(__float2bfloat16(a2));
            float h3 = __bfloat162float(__float2bfloat16(a3));
            *(uint2*)(g_ah + idx + g * 4) = make_uint2(pack_bf2(a0, a1), pack_bf2(a2, a3));
            *(uint2*)(g_al + idx + g * 4) = make_uint2(pack_bf2(a0 - h0, a1 - h1),
                                                       pack_bf2(a2 - h2, a3 - h3));
        }
    }
}

// ---------------------------------------------------------------------------
extern "C" void kernel_launch(void* const* d_in, const int* in_sizes, int n_in,
                              void* d_out, int out_size)
{
    const float* x          = (const float*)d_in[0];
    const unsigned char* mk = (const unsigned char*)d_in[1];
    float* out              = (float*)d_out;

    float *qp, *kp, *vp;
    unsigned char* mkc;
    __nv_bfloat16 *xh, *xl, *ah, *al, *wh, *wl;
    cudaGetSymbolAddress((void**)&qp, g_q);
    cudaGetSymbolAddress((void**)&kp, g_k);
    cudaGetSymbolAddress((void**)&vp, g_v);
    cudaGetSymbolAddress((void**)&mkc, g_mask);
    cudaGetSymbolAddress((void**)&xh, g_xh);
    cudaGetSymbolAddress((void**)&xl, g_xl);
    cudaGetSymbolAddress((void**)&ah, g_ah);
    cudaGetSymbolAddress((void**)&al, g_al);
    cudaGetSymbolAddress((void**)&wh, g_wh);
    cudaGetSymbolAddress((void**)&wl, g_wl);

    cudaFuncSetAttribute(gemm_kv_kernel,
                         cudaFuncAttributeMaxDynamicSharedMemorySize, GSM_TOTAL);
    cudaFuncSetAttribute(gemm_tc_kernel,
                         cudaFuncAttributeMaxDynamicSharedMemorySize, GSM_TOTAL);

    // Side stream + events for Q-GEMM / kv-chain overlap (created once; host-side,
    // no device allocation; identical work every call).
    static cudaStream_t s1 = nullptr;
    static cudaEvent_t evFork = nullptr, evJoin = nullptr;
    if (s1 == nullptr) {
        cudaStreamCreateWithFlags(&s1, cudaStreamNonBlocking);
        cudaEventCreateWithFlags(&evFork, cudaEventDisableTiming);
        cudaEventCreateWithFlags(&evJoin, cudaEventDisableTiming);
    }

    const int n4x = BT * Dc / 4;
    // 5 cheap prep launches so ncu (-s 5 -c 1) profiles the KV GEMM (6th launch).
    split_kernel<<<2048, 256>>>((const float4*)x, (uint2*)xh, (uint2*)xl, 0, n4x / 2);       // 1
    split_kernel<<<2048, 256>>>((const float4*)x, (uint2*)xh, (uint2*)xl, n4x / 2, n4x);     // 2
    splitw_kernel<<<dim3(512, 2), 256>>>((const float4*)d_in[2], (const float4*)d_in[3], 0); // 3
    splitw_kernel<<<dim3(512, 2), 256>>>((const float4*)d_in[4], (const float4*)d_in[5], 2); // 4
    mask_convert_kernel<<<64, 256>>>(mk);                                                    // 5

    // Main stream: K,V fused GEMM, then kv chain.
    gemm_kv_kernel<<<dim3(16, 128), 256, GSM_TOTAL>>>(xh, xl, kp, vp, mkc);                  // 6 <- profiled

    // Fork: Q GEMM on side stream (depends only on prep, launched after KV so the
    // scheduler fills KV's drain with Q CTAs while the kv chain runs on stream 0).
    cudaEventRecord(evFork, 0);
    cudaStreamWaitEvent(s1, evFork, 0);
    gemm_tc_kernel<<<dim3(8, 128), 256, GSM_TOTAL, s1>>>(
        xh, xl, wh + 0 * (size_t)Dc * Dc, wl + 0 * (size_t)Dc * Dc, qp, mkc, 1);
    cudaEventRecord(evJoin, s1);

    kv_partial_kernel<<<dim3(BH, 8), 256>>>();
    kv_reduce_kernel<<<BH, 256>>>();

    // Join: attn_out needs Q.
    cudaStreamWaitEvent(0, evJoin, 0);
    attn_out_kernel<<<dim3(Tc / 256, BH), 256>>>();
    gemm_tc_kernel<<<dim3(8, 128), 256, GSM_TOTAL>>>(
        ah, al, wh + 3 * (size_t)Dc * Dc, wl + 3 * (size_t)Dc * Dc, out, mkc, 0);
}

// round 14
// speedup vs baseline: 1.2545x; 1.0158x over previous
#include <cuda_runtime.h>
#include <cuda_bf16.h>
#include <math.h>
#include <stdint.h>

// Problem constants
constexpr int Bc = 4, Tc = 4096, Dc = 1024, Hc = 16, HDc = 64;
constexpr int BT = Bc * Tc;          // 16384 rows
constexpr int BH = Bc * Hc;          // 64 (b,h) pairs
constexpr int SPLIT = 32;            // total kv partial slots (8 blocks x 4 groups)

// Scratch (device globals: no allocation allowed in kernel_launch)
__device__ float g_q[BT * Dc];
__device__ float g_k[BT * Dc];
__device__ float g_v[BT * Dc];
__device__ float g_kvp[BH * SPLIT * HDc * HDc];
__device__ float g_ksp[BH * SPLIT * HDc];
__device__ float g_kv[BH * HDc * HDc];
__device__ float g_ksum[BH * HDc];
__device__ unsigned char g_mask[BT];
// bf16 hi/lo split operand buffers
__device__ __nv_bfloat16 g_xh[BT * Dc], g_xl[BT * Dc];
__device__ __nv_bfloat16 g_ah[BT * Dc], g_al[BT * Dc];
__device__ __nv_bfloat16 g_wh[4][Dc * Dc], g_wl[4][Dc * Dc];

__device__ __forceinline__ float phi(float x) {
    return x > 0.f ? x + 1.f : expf(x);
}

__device__ __forceinline__ uint32_t smem_u32(const void* p) {
    uint32_t a;
    asm("{ .reg .u64 t; cvta.to.shared.u64 t, %1; cvt.u32.u64 %0, t; }" : "=r"(a) : "l"(p));
    return a;
}

__device__ __forceinline__ uint32_t pack_bf2(float x, float y) {
    __nv_bfloat162 h = __floats2bfloat162_rn(x, y);
    return *(uint32_t*)&h;
}

__device__ __forceinline__ void cp16(uint32_t dst, const void* src) {
    asm volatile("cp.async.cg.shared.global [%0], [%1], 16;" :: "r"(dst), "l"(src));
}
#define CP_COMMIT() asm volatile("cp.async.commit_group;" ::: "memory")
#define CP_WAIT1()  asm volatile("cp.async.wait_group 1;" ::: "memory")
#define CP_WAIT0()  asm volatile("cp.async.wait_group 0;" ::: "memory")

// ---------------------------------------------------------------------------
// fp32 -> (hi, lo) bf16 split, vectorized
// ---------------------------------------------------------------------------
__global__ __launch_bounds__(256) void split_kernel(
    const float4* __restrict__ src, uint2* __restrict__ hi, uint2* __restrict__ lo,
    int i0, int n4)
{
    for (int i = i0 + blockIdx.x * 256 + threadIdx.x; i < n4; i += gridDim.x * 256) {
        float4 v = src[i];
        float hx = __bfloat162float(__float2bfloat16(v.x));
        float hy = __bfloat162float(__float2bfloat16(v.y));
        float hz = __bfloat162float(__float2bfloat16(v.z));
        float hw = __bfloat162float(__float2bfloat16(v.w));
        hi[i] = make_uint2(pack_bf2(v.x, v.y), pack_bf2(v.z, v.w));
        lo[i] = make_uint2(pack_bf2(v.x - hx, v.y - hy), pack_bf2(v.z - hz, v.w - hw));
    }
}

// two weight matrices per launch (blockIdx.y = which of the pair)
__global__ __launch_bounds__(256) void splitw_kernel(
    const float4* __restrict__ wa, const float4* __restrict__ wb, int wbase)
{
    const int wsel = wbase + blockIdx.y;
    const float4* src = blockIdx.y == 0 ? wa : wb;
    uint2* hi = (uint2*)(g_wh[wsel]);
    uint2* lo = (uint2*)(g_wl[wsel]);
    const int n4 = Dc * Dc / 4;
    for (int i = blockIdx.x * 256 + threadIdx.x; i < n4; i += gridDim.x * 256) {
        float4 v = src[i];
        float hx = __bfloat162float(__float2bfloat16(v.x));
        float hy = __bfloat162float(__float2bfloat16(v.y));
        float hz = __bfloat162float(__float2bfloat16(v.z));
        float hw = __bfloat162float(__float2bfloat16(v.w));
        hi[i] = make_uint2(pack_bf2(v.x, v.y), pack_bf2(v.z, v.w));
        lo[i] = make_uint2(pack_bf2(v.x - hx, v.y - hy), pack_bf2(v.z - hz, v.w - hw));
    }
}

// ---------------------------------------------------------------------------
// 3-term bf16-split tensor-core GEMM mainloop (shared).
// Tile 128x128, 8 warps (4m x 2n), warp tile 32x64, cp.async 3-stage, 2 CTA/SM.
// ---------------------------------------------------------------------------
constexpr int GSM_STAGE = 32768;
constexpr int NSTAGES = 3;
constexpr int GSM_TOTAL = NSTAGES * GSM_STAGE;   // 96KB -> 2 CTAs/SM

struct GemmCore {
    float acc[2][8][4];

    __device__ __forceinline__ void run(
        uint32_t sbase, char* smem,
        const __nv_bfloat16* srcA, const __nv_bfloat16* srcB,
        int tid, int wid, int lane)
    {
        const int wm = wid & 3, wn = wid >> 2;
        const int r0 = tid >> 3;
        const int part = (tid >> 2) & 1;
        const int ci = tid & 3;
        uint32_t dstA[4];
#pragma unroll
        for (int i = 0; i < 4; i++) {
            int row = r0 + 32 * i;
            dstA[i] = ((uint32_t)(row * 128 + part * 64 + ci * 16)) ^ (uint32_t)((row & 7) << 4);
        }

        auto load_stage = [&](int s, int buf) {
            uint32_t sb = sbase + buf * GSM_STAGE;
            const int koff = s * 32 + ci * 8;
#pragma unroll
            for (int i = 0; i < 4; i++) {
                int row = r0 + 32 * i;
                cp16(sb + dstA[i], srcA + (size_t)row * 1024 + koff);
                cp16(sb + 16384 + dstA[i], srcB + (size_t)row * 1024 + koff);
            }
        };

#pragma unroll
        for (int s = 0; s < NSTAGES - 1; s++) {
            load_stage(s, s);
            CP_COMMIT();
        }

#pragma unroll
        for (int mt = 0; mt < 2; mt++)
#pragma unroll
            for (int nt = 0; nt < 8; nt++)
#pragma unroll
                for (int j = 0; j < 4; j++) acc[mt][nt][j] = 0.f;

        const int lrow = lane & 7;
        const int seg = lane >> 3;
        const int segr = (seg & 1) << 3;
        const int segc = (seg & 2) << 3;

        const uint32_t swl = (uint32_t)(lrow << 4);
        uint32_t rowA[2], rowB[4], cxH[2], cxL[2];
#pragma unroll
        for (int mt = 0; mt < 2; mt++)
            rowA[mt] = (uint32_t)((wm * 32 + mt * 16 + lrow + segr) * 128);
#pragma unroll
        for (int n = 0; n < 4; n++)
            rowB[n] = (uint32_t)((wn * 64 + n * 16 + lrow + segr) * 128);
#pragma unroll
        for (int ks2 = 0; ks2 < 2; ks2++) {
            cxH[ks2] = ((uint32_t)(ks2 * 32 + segc)) ^ swl;
            cxL[ks2] = ((uint32_t)(64 + ks2 * 32 + segc)) ^ swl;
        }

        constexpr int NT = 32;
        int buf = 0;
#pragma unroll 1
        for (int t = 0; t < NT; t++) {
            CP_WAIT1();
            __syncthreads();
            if (t + NSTAGES - 1 < NT) {
                int lb = buf + NSTAGES - 1; if (lb >= NSTAGES) lb -= NSTAGES;
                load_stage(t + NSTAGES - 1, lb);
            }
            CP_COMMIT();

            const uint32_t sA = sbase + buf * GSM_STAGE;
            const uint32_t sB = sA + 16384;
            if (++buf == NSTAGES) buf = 0;

#pragma unroll
            for (int ks2 = 0; ks2 < 2; ks2++) {
                uint32_t afrH[2][4], afrL[2][4];
#pragma unroll
                for (int mt = 0; mt < 2; mt++) {
                    asm volatile("ldmatrix.sync.aligned.m8n8.x4.shared.b16 {%0,%1,%2,%3}, [%4];"
                        : "=r"(afrH[mt][0]), "=r"(afrH[mt][1]), "=r"(afrH[mt][2]), "=r"(afrH[mt][3])
                        : "r"(sA + rowA[mt] + cxH[ks2]));
                    asm volatile("ldmatrix.sync.aligned.m8n8.x4.shared.b16 {%0,%1,%2,%3}, [%4];"
                        : "=r"(afrL[mt][0]), "=r"(afrL[mt][1]), "=r"(afrL[mt][2]), "=r"(afrL[mt][3])
                        : "r"(sA + rowA[mt] + cxL[ks2]));
                }
                uint32_t bfrH[4][4], bfrL[4][4];
#pragma unroll
                for (int nt2 = 0; nt2 < 4; nt2++) {
                    asm volatile("ldmatrix.sync.aligned.m8n8.x4.shared.b16 {%0,%1,%2,%3}, [%4];"
                        : "=r"(bfrH[nt2][0]), "=r"(bfrH[nt2][1]), "=r"(bfrH[nt2][2]), "=r"(bfrH[nt2][3])
                        : "r"(sB + rowB[nt2] + cxH[ks2]));
                    asm volatile("ldmatrix.sync.aligned.m8n8.x4.shared.b16 {%0,%1,%2,%3}, [%4];"
                        : "=r"(bfrL[nt2][0]), "=r"(bfrL[nt2][1]), "=r"(bfrL[nt2][2]), "=r"(bfrL[nt2][3])
                        : "r"(sB + rowB[nt2] + cxL[ks2]));
                }

#pragma unroll
                for (int mt = 0; mt < 2; mt++)
#pragma unroll
                    for (int nt = 0; nt < 8; nt++) {
                        const int g = nt >> 1, h = nt & 1;
                        asm volatile(
                            "mma.sync.aligned.m16n8k16.row.col.f32.bf16.bf16.f32 "
                            "{%0,%1,%2,%3}, {%4,%5,%6,%7}, {%8,%9}, {%0,%1,%2,%3};"
                            : "+f"(acc[mt][nt][0]), "+f"(acc[mt][nt][1]),
                              "+f"(acc[mt][nt][2]), "+f"(acc[mt][nt][3])
                            : "r"(afrH[mt][0]), "r"(afrH[mt][1]), "r"(afrH[mt][2]), "r"(afrH[mt][3]),
                              "r"(bfrH[g][h]), "r"(bfrH[g][h + 2]));
                        asm volatile(
                            "mma.sync.aligned.m16n8k16.row.col.f32.bf16.bf16.f32 "
                            "{%0,%1,%2,%3}, {%4,%5,%6,%7}, {%8,%9}, {%0,%1,%2,%3};"
                            : "+f"(acc[mt][nt][0]), "+f"(acc[mt][nt][1]),
                              "+f"(acc[mt][nt][2]), "+f"(acc[mt][nt][3])
                            : "r"(afrL[mt][0]), "r"(afrL[mt][1]), "r"(afrL[mt][2]), "r"(afrL[mt][3]),
                              "r"(bfrH[g][h]), "r"(bfrH[g][h + 2]));
                        asm volatile(
                            "mma.sync.aligned.m16n8k16.row.col.f32.bf16.bf16.f32 "
                            "{%0,%1,%2,%3}, {%4,%5,%6,%7}, {%8,%9}, {%0,%1,%2,%3};"
                            : "+f"(acc[mt][nt][0]), "+f"(acc[mt][nt][1]),
                              "+f"(acc[mt][nt][2]), "+f"(acc[mt][nt][3])
                            : "r"(afrH[mt][0]), "r"(afrH[mt][1]), "r"(afrH[mt][2]), "r"(afrH[mt][3]),
                              "r"(bfrL[g][h]), "r"(bfrL[g][h + 2]));
                    }
            }
        }
    }

    __device__ __forceinline__ void epilogue(
        float* C, const unsigned char* mask, int op,
        int brow, int bcol, int wid, int lane)
    {
        const int wm = wid & 3, wn = wid >> 2;
        const int r0e = brow * 128 + wm * 32 + (lane >> 2);
        const int c0 = bcol * 128 + wn * 64 + (lane & 3) * 2;
        const bool do_phi = (op == 1 || op == 2);
        const bool do_msk = (op >= 2);
#pragma unroll
        for (int mt = 0; mt < 2; mt++) {
            const int r = r0e + mt * 16;
            const bool mz0 = do_msk && (mask[r] != 0);
            const bool mz1 = do_msk && (mask[r + 8] != 0);
#pragma unroll
            for (int nt = 0; nt < 8; nt++) {
                float2 v0 = make_float2(acc[mt][nt][0], acc[mt][nt][1]);
                float2 v1 = make_float2(acc[mt][nt][2], acc[mt][nt][3]);
                if (do_phi) {
                    v0.x = phi(v0.x); v0.y = phi(v0.y);
                    v1.x = phi(v1.x); v1.y = phi(v1.y);
                }
                if (mz0) { v0.x = 0.f; v0.y = 0.f; }
                if (mz1) { v1.x = 0.f; v1.y = 0.f; }
                *(float2*)(C + (size_t)r * 1024 + c0 + nt * 8) = v0;
                *(float2*)(C + (size_t)(r + 8) * 1024 + c0 + nt * 8) = v1;
            }
        }
    }
};

// Fused K/V GEMM: grid (16, 128). blockIdx.x>>3 selects K (W1, op2) / V (W2, op3).
__global__ __launch_bounds__(256, 2) void gemm_kv_kernel(
    const __nv_bfloat16* __restrict__ Ah, const __nv_bfloat16* __restrict__ Al,
    float* __restrict__ C1, float* __restrict__ C2,
    const unsigned char* __restrict__ mask)
{
    extern __shared__ __align__(1024) char smem[];
    const uint32_t sbase = smem_u32(smem);
    const int tid = threadIdx.x;
    const int wid = tid >> 5, lane = tid & 31;
    const int brow = blockIdx.y;
    const int sel = blockIdx.x >> 3;         // 0=K, 1=V
    const int bcol = blockIdx.x & 7;

    const int part = (tid >> 2) & 1;
    const __nv_bfloat16* srcA = (part ? Al : Ah) + (size_t)(brow * 128) * 1024;
    const __nv_bfloat16* srcB = (part ? g_wl[sel + 1] : g_wh[sel + 1]) + (size_t)(bcol * 128) * 1024;

    GemmCore core;
    core.run(sbase, smem, srcA, srcB, tid, wid, lane);

    float* C = sel == 0 ? C1 : C2;
    core.epilogue(C, mask, sel + 2, brow, bcol, wid, lane);
}

// Plain GEMM (Q projection op=1, Wo projection op=0).
__global__ __launch_bounds__(256, 2) void gemm_tc_kernel(
    const __nv_bfloat16* __restrict__ Ah, const __nv_bfloat16* __restrict__ Al,
    const __nv_bfloat16* __restrict__ Bh, const __nv_bfloat16* __restrict__ Bl,
    float* __restrict__ C, const unsigned char* __restrict__ mask, int op)
{
    extern __shared__ __align__(1024) char smem[];
    const uint32_t sbase = smem_u32(smem);
    const int tid = threadIdx.x;
    const int wid = tid >> 5, lane = tid & 31;
    const int brow = blockIdx.y, bcol = blockIdx.x;

    const int part = (tid >> 2) & 1;
    const __nv_bfloat16* srcA = (part ? Al : Ah) + (size_t)(brow * 128) * 1024;
    const __nv_bfloat16* srcB = (part ? Bl : Bh) + (size_t)(bcol * 128) * 1024;

    GemmCore core;
    core.run(sbase, smem, srcA, srcB, tid, wid, lane);
    core.epilogue(C, mask, op, brow, bcol, wid, lane);
}

// ---------------------------------------------------------------------------
// Mask normalization (dtype-agnostic) -> uint8 0/1
// ---------------------------------------------------------------------------
__global__ __launch_bounds__(256) void mask_convert_kernel(const unsigned char* __restrict__ mraw)
{
    __shared__ int s_float, s_odd;
    if (threadIdx.x == 0) { s_float = 0; s_odd = 0; }
    __syncthreads();
    for (int i = threadIdx.x; i < 4096; i += 256) {
        unsigned char v = mraw[i];
        if (v == 0x3F) s_float = 1;
        if (v != 0 && (i & 3) != 0) s_odd = 1;
    }
    __syncthreads();
    const int dtype = s_float ? 2 : (s_odd ? 0 : 1);

    const int m0 = blockIdx.x * 256 + threadIdx.x;
    for (int m = m0; m < BT; m += 64 * 256) {
        unsigned char r;
        if (dtype == 0)      r = (mraw[m] != 0);
        else if (dtype == 1) r = (((const int*)mraw)[m] != 0);
        else                 r = (((const float*)mraw)[m] != 0.0f);
        g_mask[m] = r;
    }
}

// ---------------------------------------------------------------------------
// kv partial, register-blocked 4d x 16e per thread. grid (BH, 8).
// ---------------------------------------------------------------------------
__global__ __launch_bounds__(256) void kv_partial_kernel()
{
    const int tid = threadIdx.x;
    const int bh = blockIdx.x, sy = blockIdx.y;
    const int b = bh >> 4, h = bh & 15;
    const int t0 = sy * 512;

    __shared__ __align__(16) float Ks[2][32][64];
    __shared__ __align__(16) float Vs[2][32][64];
    const uint32_t sK = smem_u32(&Ks[0][0][0]);
    const uint32_t sV = smem_u32(&Vs[0][0][0]);

    const int q  = tid >> 6;
    const int r  = tid & 63;
    const int d0 = (r >> 2) * 4;
    const int e0 = (r & 3) * 16;

    float acc[4][16];
#pragma unroll
    for (int j = 0; j < 4; j++)
#pragma unroll
        for (int i = 0; i < 16; i++) acc[j][i] = 0.f;
    float ks[4] = {0.f, 0.f, 0.f, 0.f};

    const size_t base = ((size_t)b * Tc) * Dc + h * 64;

    const int tl0 = tid >> 4,         c40 = (tid & 15) * 4;
    const int tl1 = (tid + 256) >> 4, c41 = ((tid + 256) & 15) * 4;
    const uint32_t so0 = (uint32_t)((tl0 * 64 + c40) * 4);
    const uint32_t so1 = (uint32_t)((tl1 * 64 + c41) * 4);

    auto load_chunk = [&](int c, int bufsel) {
        uint32_t kb = sK + bufsel * 8192, vb = sV + bufsel * 8192;
        size_t g0 = base + (size_t)(t0 + c * 32 + tl0) * Dc + c40;
        size_t g1 = base + (size_t)(t0 + c * 32 + tl1) * Dc + c41;
        cp16(kb + so0, g_k + g0);
        cp16(vb + so0, g_v + g0);
        cp16(kb + so1, g_k + g1);
        cp16(vb + so1, g_v + g1);
    };

    load_chunk(0, 0);
    CP_COMMIT();

#pragma unroll 1
    for (int c = 0; c < 16; c++) {
        if (c < 15) {
            load_chunk(c + 1, (c + 1) & 1);
            CP_COMMIT();
            CP_WAIT1();
        } else {
            CP_WAIT0();
        }
        __syncthreads();
        const int cb = c & 1;
#pragma unroll
        for (int tt = 0; tt < 8; tt++) {
            const int t = q * 8 + tt;
            float4 kd = *(const float4*)&Ks[cb][t][d0];
            float4 v0 = *(const float4*)&Vs[cb][t][e0];
            float4 v1 = *(const float4*)&Vs[cb][t][e0 + 4];
            float4 v2 = *(const float4*)&Vs[cb][t][e0 + 8];
            float4 v3 = *(const float4*)&Vs[cb][t][e0 + 12];
            ks[0] += kd.x; ks[1] += kd.y; ks[2] += kd.z; ks[3] += kd.w;
            const float kv4[4] = {kd.x, kd.y, kd.z, kd.w};
            const float vv[16] = {v0.x, v0.y, v0.z, v0.w, v1.x, v1.y, v1.z, v1.w,
                                  v2.x, v2.y, v2.z, v2.w, v3.x, v3.y, v3.z, v3.w};
#pragma unroll
            for (int j = 0; j < 4; j++)
#pragma unroll
                for (int i = 0; i < 16; i++)
                    acc[j][i] = fmaf(kv4[j], vv[i], acc[j][i]);
        }
        __syncthreads();
    }

    const int slot = bh * SPLIT + sy * 4 + q;
    float* outp = g_kvp + (size_t)slot * 4096;
#pragma unroll
    for (int j = 0; j < 4; j++) {
        float* rp = outp + (d0 + j) * 64 + e0;
        *(float4*)(rp + 0)  = make_float4(acc[j][0], acc[j][1], acc[j][2], acc[j][3]);
        *(float4*)(rp + 4)  = make_float4(acc[j][4], acc[j][5], acc[j][6], acc[j][7]);
        *(float4*)(rp + 8)  = make_float4(acc[j][8], acc[j][9], acc[j][10], acc[j][11]);
        *(float4*)(rp + 12) = make_float4(acc[j][12], acc[j][13], acc[j][14], acc[j][15]);
    }
    if ((r & 3) == 0) {
#pragma unroll
        for (int j = 0; j < 4; j++)
            g_ksp[slot * 64 + d0 + j] = ks[j];
    }
}

// ---------------------------------------------------------------------------
__global__ __launch_bounds__(256) void kv_reduce_kernel()
{
    const int bh = blockIdx.x, tid = threadIdx.x;
#pragma unroll
    for (int j = 0; j < 4; j++) {
        int off = tid * 16 + j * 4;
        float4 s = make_float4(0.f, 0.f, 0.f, 0.f);
#pragma unroll
        for (int sp = 0; sp < SPLIT; sp++) {
            float4 p = *(const float4*)(g_kvp + ((size_t)(bh * SPLIT + sp)) * 4096 + off);
            s.x += p.x; s.y += p.y; s.z += p.z; s.w += p.w;
        }
        *(float4*)(g_kv + (size_t)bh * 4096 + off) = s;
    }
    if (tid < 64) {
        float s = 0.f;
#pragma unroll
        for (int sp = 0; sp < SPLIT; sp++)
            s += g_ksp[(bh * SPLIT + sp) * 64 + tid];
        g_ksum[bh * 64 + tid] = s;
    }
}

// ---------------------------------------------------------------------------
// attn out, register-blocked 4 t-rows x 16 e-cols; writes bf16 hi/lo split.
// ---------------------------------------------------------------------------
constexpr int QS_STRIDE = 260;

__global__ __launch_bounds__(256) void attn_out_kernel()
{
    const int tid = threadIdx.x;
    const int bh = blockIdx.y;
    const int b = bh >> 4, h = bh & 15;
    const int t0 = blockIdx.x * 256;

    __shared__ __align__(16) float KV[4096];
    __shared__ __align__(16) float Qs[16][QS_STRIDE];
    __shared__ float Ksm[64];

#pragma unroll
    for (int j = 0; j < 4; j++) {
        int f = tid + j * 256;
        *(float4*)&KV[f * 4] = *(const float4*)(g_kv + (size_t)bh * 4096 + f * 4);
    }
    if (tid < 64) Ksm[tid] = g_ksum[bh * 64 + tid];

    const size_t base = ((size_t)b * Tc) * Dc + h * 64;
    const int tl4 = tid >> 2;
    const int e0 = (tid & 3) * 16;

    float acc[4][16];
#pragma unroll
    for (int j = 0; j < 4; j++)
#pragma unroll
        for (int i = 0; i < 16; i++) acc[j][i] = 0.f;
    float nrm[4] = {0.f, 0.f, 0.f, 0.f};

#pragma unroll 1
    for (int dc = 0; dc < 4; dc++) {
        __syncthreads();
#pragma unroll
        for (int j = 0; j < 16; j++) {
            int idx = tid + j * 256;
            int d = idx & 15, t = idx >> 4;
            Qs[d][t] = g_q[base + (size_t)(t0 + t) * Dc + dc * 16 + d];
        }
        __syncthreads();
#pragma unroll
        for (int d2 = 0; d2 < 16; d2++) {
            const int dg = dc * 16 + d2;
            float4 qv = *(const float4*)&Qs[d2][tl4 * 4];
            const float km = Ksm[dg];
            const float4* kvp = (const float4*)&KV[dg * 64 + e0];
            float4 w0 = kvp[0], w1 = kvp[1], w2 = kvp[2], w3 = kvp[3];
            const float qq[4] = {qv.x, qv.y, qv.z, qv.w};
            const float vv[16] = {w0.x, w0.y, w0.z, w0.w, w1.x, w1.y, w1.z, w1.w,
                                  w2.x, w2.y, w2.z, w2.w, w3.x, w3.y, w3.z, w3.w};
#pragma unroll
            for (int j = 0; j < 4; j++) {
                nrm[j] = fmaf(qq[j], km, nrm[j]);
#pragma unroll
                for (int i = 0; i < 16; i++)
                    acc[j][i] = fmaf(qq[j], vv[i], acc[j][i]);
            }
        }
    }

#pragma unroll
    for (int j = 0; j < 4; j++) {
        const float inv = 1.f / fmaxf(nrm[j], 1e-6f);
        const size_t idx = base + (size_t)(t0 + tl4 * 4 + j) * Dc + e0;
#pragma unroll
        for (int g = 0; g < 4; g++) {
            float a0 = acc[j][g * 4 + 0] * inv, a1 = acc[j][g * 4 + 1] * inv;
            float a2 = acc[j][g * 4 + 2] * inv, a3 = acc[j][g * 4 + 3] * inv;
            float h0 = __bfloat162float(__float2bfloat16(a0));
            float h1 = __bfloat162float(__float2bfloat16(a1));
            float h2 = __bfloat162float(__float2bfloat16(a2));
            float h3 = __bfloat162float(__float2bfloat16(a3));
            *(uint2*)(g_ah + idx + g * 4) = make_uint2(pack_bf2(a0, a1), pack_bf2(a2, a3));
            *(uint2*)(g_al + idx + g * 4) = make_uint2(pack_bf2(a0 - h0, a1 - h1),
                                                       pack_bf2(a2 - h2, a3 - h3));
        }
    }
}

// ---------------------------------------------------------------------------
extern "C" void kernel_launch(void* const* d_in, const int* in_sizes, int n_in,
                              void* d_out, int out_size)
{
    const float* x          = (const float*)d_in[0];
    const unsigned char* mk = (const unsigned char*)d_in[1];
    float* out              = (float*)d_out;

    float *qp, *kp, *vp;
    unsigned char* mkc;
    __nv_bfloat16 *xh, *xl, *ah, *al, *wh, *wl;
    cudaGetSymbolAddress((void**)&qp, g_q);
    cudaGetSymbolAddress((void**)&kp, g_k);
    cudaGetSymbolAddress((void**)&vp, g_v);
    cudaGetSymbolAddress((void**)&mkc, g_mask);
    cudaGetSymbolAddress((void**)&xh, g_xh);
    cudaGetSymbolAddress((void**)&xl, g_xl);
    cudaGetSymbolAddress((void**)&ah, g_ah);
    cudaGetSymbolAddress((void**)&al, g_al);
    cudaGetSymbolAddress((void**)&wh, g_wh);
    cudaGetSymbolAddress((void**)&wl, g_wl);

    cudaFuncSetAttribute(gemm_kv_kernel,
                         cudaFuncAttributeMaxDynamicSharedMemorySize, GSM_TOTAL);
    cudaFuncSetAttribute(gemm_tc_kernel,
                         cudaFuncAttributeMaxDynamicSharedMemorySize, GSM_TOTAL);

    // Side stream + events (created once; host-side only; identical work per call).
    static cudaStream_t s1 = nullptr;
    static cudaEvent_t evFork = nullptr, evX = nullptr, evPrep = nullptr, evJoin = nullptr;
    if (s1 == nullptr) {
        cudaStreamCreateWithFlags(&s1, cudaStreamNonBlocking);
        cudaEventCreateWithFlags(&evFork, cudaEventDisableTiming);
        cudaEventCreateWithFlags(&evX, cudaEventDisableTiming);
        cudaEventCreateWithFlags(&evPrep, cudaEventDisableTiming);
        cudaEventCreateWithFlags(&evJoin, cudaEventDisableTiming);
    }

    const int n4x = BT * Dc / 4;

    // Fork side stream from stream 0 (capture-safe: s1 first waits on s0 event).
    cudaEventRecord(evFork, 0);
    cudaStreamWaitEvent(s1, evFork, 0);

    // s1: W splits + mask (independent of x).
    splitw_kernel<<<dim3(512, 2), 256, 0, s1>>>((const float4*)d_in[2], (const float4*)d_in[3], 0);
    splitw_kernel<<<dim3(512, 2), 256, 0, s1>>>((const float4*)d_in[4], (const float4*)d_in[5], 2);
    mask_convert_kernel<<<64, 256, 0, s1>>>(mk);
    cudaEventRecord(evPrep, s1);

    // s0: x split halves (concurrent with s1 prep).
    split_kernel<<<2048, 256>>>((const float4*)x, (uint2*)xh, (uint2*)xl, 0, n4x / 2);
    split_kernel<<<2048, 256>>>((const float4*)x, (uint2*)xh, (uint2*)xl, n4x / 2, n4x);
    cudaEventRecord(evX, 0);

    // s1: Q GEMM, concurrent with KV GEMM on s0 (needs x split + W0 split).
    cudaStreamWaitEvent(s1, evX, 0);
    gemm_tc_kernel<<<dim3(8, 128), 256, GSM_TOTAL, s1>>>(
        xh, xl, wh + 0 * (size_t)Dc * Dc, wl + 0 * (size_t)Dc * Dc, qp, mkc, 1);
    cudaEventRecord(evJoin, s1);

    // s0: KV GEMM (needs x split on s0 + W1/W2 splits + mask from s1), then kv chain.
    cudaStreamWaitEvent(0, evPrep, 0);
    gemm_kv_kernel<<<dim3(16, 128), 256, GSM_TOTAL>>>(xh, xl, kp, vp, mkc);
    kv_partial_kernel<<<dim3(BH, 8), 256>>>();
    kv_reduce_kernel<<<BH, 256>>>();

    // Join: attn_out needs Q.
    cudaStreamWaitEvent(0, evJoin, 0);
    attn_out_kernel<<<dim3(Tc / 256, BH), 256>>>();
    gemm_tc_kernel<<<dim3(8, 128), 256, GSM_TOTAL>>>(
        ah, al, wh + 3 * (size_t)Dc * Dc, wl + 3 * (size_t)Dc * Dc, out, mkc, 0);
}

// round 15
// speedup vs baseline: 1.2548x; 1.0002x over previous
#include <cuda_runtime.h>
#include <cuda_bf16.h>
#include <math.h>
#include <stdint.h>

// Problem constants
constexpr int Bc = 4, Tc = 4096, Dc = 1024, Hc = 16, HDc = 64;
constexpr int BT = Bc * Tc;          // 16384 rows
constexpr int BH = Bc * Hc;          // 64 (b,h) pairs
constexpr int SPLIT = 32;            // total kv partial slots (8 blocks x 4 groups)

// Scratch (device globals: no allocation allowed in kernel_launch)
__device__ float g_q[BT * Dc];
__device__ float g_k[BT * Dc];
__device__ float g_v[BT * Dc];
__device__ float g_kvp[BH * SPLIT * HDc * HDc];
__device__ float g_ksp[BH * SPLIT * HDc];
__device__ float g_kv[BH * HDc * HDc];
__device__ float g_ksum[BH * HDc];
__device__ unsigned char g_mask[BT];
// bf16 hi/lo split operand buffers
__device__ __nv_bfloat16 g_xh[BT * Dc], g_xl[BT * Dc];
__device__ __nv_bfloat16 g_ah[BT * Dc], g_al[BT * Dc];
__device__ __nv_bfloat16 g_wh[4][Dc * Dc], g_wl[4][Dc * Dc];

__device__ __forceinline__ float phi(float x) {
    return x > 0.f ? x + 1.f : expf(x);
}

__device__ __forceinline__ uint32_t smem_u32(const void* p) {
    uint32_t a;
    asm("{ .reg .u64 t; cvta.to.shared.u64 t, %1; cvt.u32.u64 %0, t; }" : "=r"(a) : "l"(p));
    return a;
}

__device__ __forceinline__ uint32_t pack_bf2(float x, float y) {
    __nv_bfloat162 h = __floats2bfloat162_rn(x, y);
    return *(uint32_t*)&h;
}

__device__ __forceinline__ void cp16(uint32_t dst, const void* src) {
    asm volatile("cp.async.cg.shared.global [%0], [%1], 16;" :: "r"(dst), "l"(src));
}
#define CP_COMMIT() asm volatile("cp.async.commit_group;" ::: "memory")
#define CP_WAIT1()  asm volatile("cp.async.wait_group 1;" ::: "memory")
#define CP_WAIT0()  asm volatile("cp.async.wait_group 0;" ::: "memory")

// ---------------------------------------------------------------------------
// fp32 -> (hi, lo) bf16 split, vectorized
// ---------------------------------------------------------------------------
__global__ __launch_bounds__(256) void split_kernel(
    const float4* __restrict__ src, uint2* __restrict__ hi, uint2* __restrict__ lo,
    int i0, int n4)
{
    for (int i = i0 + blockIdx.x * 256 + threadIdx.x; i < n4; i += gridDim.x * 256) {
        float4 v = src[i];
        float hx = __bfloat162float(__float2bfloat16(v.x));
        float hy = __bfloat162float(__float2bfloat16(v.y));
        float hz = __bfloat162float(__float2bfloat16(v.z));
        float hw = __bfloat162float(__float2bfloat16(v.w));
        hi[i] = make_uint2(pack_bf2(v.x, v.y), pack_bf2(v.z, v.w));
        lo[i] = make_uint2(pack_bf2(v.x - hx, v.y - hy), pack_bf2(v.z - hz, v.w - hw));
    }
}

// two weight matrices per launch (blockIdx.y = which of the pair)
__global__ __launch_bounds__(256) void splitw_kernel(
    const float4* __restrict__ wa, const float4* __restrict__ wb, int wbase)
{
    const int wsel = wbase + blockIdx.y;
    const float4* src = blockIdx.y == 0 ? wa : wb;
    uint2* hi = (uint2*)(g_wh[wsel]);
    uint2* lo = (uint2*)(g_wl[wsel]);
    const int n4 = Dc * Dc / 4;
    for (int i = blockIdx.x * 256 + threadIdx.x; i < n4; i += gridDim.x * 256) {
        float4 v = src[i];
        float hx = __bfloat162float(__float2bfloat16(v.x));
        float hy = __bfloat162float(__float2bfloat16(v.y));
        float hz = __bfloat162float(__float2bfloat16(v.z));
        float hw = __bfloat162float(__float2bfloat16(v.w));
        hi[i] = make_uint2(pack_bf2(v.x, v.y), pack_bf2(v.z, v.w));
        lo[i] = make_uint2(pack_bf2(v.x - hx, v.y - hy), pack_bf2(v.z - hz, v.w - hw));
    }
}

// ---------------------------------------------------------------------------
// 3-term bf16-split tensor-core GEMM mainloop (shared).
// Tile 128x128, 8 warps (4m x 2n), warp tile 32x64, cp.async 3-stage, 2 CTA/SM.
// MMA issue order is TERM-MAJOR: 16 independent MMAs between successive writes
// to any accumulator (dependency distance 3 -> 16).
// ---------------------------------------------------------------------------
constexpr int GSM_STAGE = 32768;
constexpr int NSTAGES = 3;
constexpr int GSM_TOTAL = NSTAGES * GSM_STAGE;   // 96KB -> 2 CTAs/SM

struct GemmCore {
    float acc[2][8][4];

    __device__ __forceinline__ void run(
        uint32_t sbase, char* smem,
        const __nv_bfloat16* srcA, const __nv_bfloat16* srcB,
        int tid, int wid, int lane)
    {
        const int wm = wid & 3, wn = wid >> 2;
        const int r0 = tid >> 3;
        const int part = (tid >> 2) & 1;
        const int ci = tid & 3;
        uint32_t dstA[4];
#pragma unroll
        for (int i = 0; i < 4; i++) {
            int row = r0 + 32 * i;
            dstA[i] = ((uint32_t)(row * 128 + part * 64 + ci * 16)) ^ (uint32_t)((row & 7) << 4);
        }

        auto load_stage = [&](int s, int buf) {
            uint32_t sb = sbase + buf * GSM_STAGE;
            const int koff = s * 32 + ci * 8;
#pragma unroll
            for (int i = 0; i < 4; i++) {
                int row = r0 + 32 * i;
                cp16(sb + dstA[i], srcA + (size_t)row * 1024 + koff);
                cp16(sb + 16384 + dstA[i], srcB + (size_t)row * 1024 + koff);
            }
        };

#pragma unroll
        for (int s = 0; s < NSTAGES - 1; s++) {
            load_stage(s, s);
            CP_COMMIT();
        }

#pragma unroll
        for (int mt = 0; mt < 2; mt++)
#pragma unroll
            for (int nt = 0; nt < 8; nt++)
#pragma unroll
                for (int j = 0; j < 4; j++) acc[mt][nt][j] = 0.f;

        const int lrow = lane & 7;
        const int seg = lane >> 3;
        const int segr = (seg & 1) << 3;
        const int segc = (seg & 2) << 3;

        const uint32_t swl = (uint32_t)(lrow << 4);
        uint32_t rowA[2], rowB[4], cxH[2], cxL[2];
#pragma unroll
        for (int mt = 0; mt < 2; mt++)
            rowA[mt] = (uint32_t)((wm * 32 + mt * 16 + lrow + segr) * 128);
#pragma unroll
        for (int n = 0; n < 4; n++)
            rowB[n] = (uint32_t)((wn * 64 + n * 16 + lrow + segr) * 128);
#pragma unroll
        for (int ks2 = 0; ks2 < 2; ks2++) {
            cxH[ks2] = ((uint32_t)(ks2 * 32 + segc)) ^ swl;
            cxL[ks2] = ((uint32_t)(64 + ks2 * 32 + segc)) ^ swl;
        }

        constexpr int NT = 32;
        int buf = 0;
#pragma unroll 1
        for (int t = 0; t < NT; t++) {
            CP_WAIT1();
            __syncthreads();
            if (t + NSTAGES - 1 < NT) {
                int lb = buf + NSTAGES - 1; if (lb >= NSTAGES) lb -= NSTAGES;
                load_stage(t + NSTAGES - 1, lb);
            }
            CP_COMMIT();

            const uint32_t sA = sbase + buf * GSM_STAGE;
            const uint32_t sB = sA + 16384;
            if (++buf == NSTAGES) buf = 0;

#pragma unroll
            for (int ks2 = 0; ks2 < 2; ks2++) {
                uint32_t afrH[2][4], afrL[2][4];
#pragma unroll
                for (int mt = 0; mt < 2; mt++) {
                    asm volatile("ldmatrix.sync.aligned.m8n8.x4.shared.b16 {%0,%1,%2,%3}, [%4];"
                        : "=r"(afrH[mt][0]), "=r"(afrH[mt][1]), "=r"(afrH[mt][2]), "=r"(afrH[mt][3])
                        : "r"(sA + rowA[mt] + cxH[ks2]));
                    asm volatile("ldmatrix.sync.aligned.m8n8.x4.shared.b16 {%0,%1,%2,%3}, [%4];"
                        : "=r"(afrL[mt][0]), "=r"(afrL[mt][1]), "=r"(afrL[mt][2]), "=r"(afrL[mt][3])
                        : "r"(sA + rowA[mt] + cxL[ks2]));
                }
                uint32_t bfrH[4][4], bfrL[4][4];
#pragma unroll
                for (int nt2 = 0; nt2 < 4; nt2++) {
                    asm volatile("ldmatrix.sync.aligned.m8n8.x4.shared.b16 {%0,%1,%2,%3}, [%4];"
                        : "=r"(bfrH[nt2][0]), "=r"(bfrH[nt2][1]), "=r"(bfrH[nt2][2]), "=r"(bfrH[nt2][3])
                        : "r"(sB + rowB[nt2] + cxH[ks2]));
                    asm volatile("ldmatrix.sync.aligned.m8n8.x4.shared.b16 {%0,%1,%2,%3}, [%4];"
                        : "=r"(bfrL[nt2][0]), "=r"(bfrL[nt2][1]), "=r"(bfrL[nt2][2]), "=r"(bfrL[nt2][3])
                        : "r"(sB + rowB[nt2] + cxL[ks2]));
                }

                // ---- 48 MMAs, term-major (16 independent MMAs per term) ----
#pragma unroll
                for (int term = 0; term < 3; term++) {
                    const uint32_t (*af)[4] = (term == 1) ? afrL : afrH;
                    const uint32_t (*bf)[4] = (term == 2) ? bfrL : bfrH;
#pragma unroll
                    for (int mt = 0; mt < 2; mt++)
#pragma unroll
                        for (int nt = 0; nt < 8; nt++) {
                            const int g = nt >> 1, h = nt & 1;
                            asm volatile(
                                "mma.sync.aligned.m16n8k16.row.col.f32.bf16.bf16.f32 "
                                "{%0,%1,%2,%3}, {%4,%5,%6,%7}, {%8,%9}, {%0,%1,%2,%3};"
                                : "+f"(acc[mt][nt][0]), "+f"(acc[mt][nt][1]),
                                  "+f"(acc[mt][nt][2]), "+f"(acc[mt][nt][3])
                                : "r"(af[mt][0]), "r"(af[mt][1]), "r"(af[mt][2]), "r"(af[mt][3]),
                                  "r"(bf[g][h]), "r"(bf[g][h + 2]));
                        }
                }
            }
        }
    }

    __device__ __forceinline__ void epilogue(
        float* C, const unsigned char* mask, int op,
        int brow, int bcol, int wid, int lane)
    {
        const int wm = wid & 3, wn = wid >> 2;
        const int r0e = brow * 128 + wm * 32 + (lane >> 2);
        const int c0 = bcol * 128 + wn * 64 + (lane & 3) * 2;
        const bool do_phi = (op == 1 || op == 2);
        const bool do_msk = (op >= 2);
#pragma unroll
        for (int mt = 0; mt < 2; mt++) {
            const int r = r0e + mt * 16;
            const bool mz0 = do_msk && (mask[r] != 0);
            const bool mz1 = do_msk && (mask[r + 8] != 0);
#pragma unroll
            for (int nt = 0; nt < 8; nt++) {
                float2 v0 = make_float2(acc[mt][nt][0], acc[mt][nt][1]);
                float2 v1 = make_float2(acc[mt][nt][2], acc[mt][nt][3]);
                if (do_phi) {
                    v0.x = phi(v0.x); v0.y = phi(v0.y);
                    v1.x = phi(v1.x); v1.y = phi(v1.y);
                }
                if (mz0) { v0.x = 0.f; v0.y = 0.f; }
                if (mz1) { v1.x = 0.f; v1.y = 0.f; }
                *(float2*)(C + (size_t)r * 1024 + c0 + nt * 8) = v0;
                *(float2*)(C + (size_t)(r + 8) * 1024 + c0 + nt * 8) = v1;
            }
        }
    }
};

// Fused K/V GEMM: grid (16, 128). blockIdx.x>>3 selects K (W1, op2) / V (W2, op3).
__global__ __launch_bounds__(256, 2) void gemm_kv_kernel(
    const __nv_bfloat16* __restrict__ Ah, const __nv_bfloat16* __restrict__ Al,
    float* __restrict__ C1, float* __restrict__ C2,
    const unsigned char* __restrict__ mask)
{
    extern __shared__ __align__(1024) char smem[];
    const uint32_t sbase = smem_u32(smem);
    const int tid = threadIdx.x;
    const int wid = tid >> 5, lane = tid & 31;
    const int brow = blockIdx.y;
    const int sel = blockIdx.x >> 3;         // 0=K, 1=V
    const int bcol = blockIdx.x & 7;

    const int part = (tid >> 2) & 1;
    const __nv_bfloat16* srcA = (part ? Al : Ah) + (size_t)(brow * 128) * 1024;
    const __nv_bfloat16* srcB = (part ? g_wl[sel + 1] : g_wh[sel + 1]) + (size_t)(bcol * 128) * 1024;

    GemmCore core;
    core.run(sbase, smem, srcA, srcB, tid, wid, lane);

    float* C = sel == 0 ? C1 : C2;
    core.epilogue(C, mask, sel + 2, brow, bcol, wid, lane);
}

// Plain GEMM (Q projection op=1, Wo projection op=0).
__global__ __launch_bounds__(256, 2) void gemm_tc_kernel(
    const __nv_bfloat16* __restrict__ Ah, const __nv_bfloat16* __restrict__ Al,
    const __nv_bfloat16* __restrict__ Bh, const __nv_bfloat16* __restrict__ Bl,
    float* __restrict__ C, const unsigned char* __restrict__ mask, int op)
{
    extern __shared__ __align__(1024) char smem[];
    const uint32_t sbase = smem_u32(smem);
    const int tid = threadIdx.x;
    const int wid = tid >> 5, lane = tid & 31;
    const int brow = blockIdx.y, bcol = blockIdx.x;

    const int part = (tid >> 2) & 1;
    const __nv_bfloat16* srcA = (part ? Al : Ah) + (size_t)(brow * 128) * 1024;
    const __nv_bfloat16* srcB = (part ? Bl : Bh) + (size_t)(bcol * 128) * 1024;

    GemmCore core;
    core.run(sbase, smem, srcA, srcB, tid, wid, lane);
    core.epilogue(C, mask, op, brow, bcol, wid, lane);
}

// ---------------------------------------------------------------------------
// Mask normalization (dtype-agnostic) -> uint8 0/1
// ---------------------------------------------------------------------------
__global__ __launch_bounds__(256) void mask_convert_kernel(const unsigned char* __restrict__ mraw)
{
    __shared__ int s_float, s_odd;
    if (threadIdx.x == 0) { s_float = 0; s_odd = 0; }
    __syncthreads();
    for (int i = threadIdx.x; i < 4096; i += 256) {
        unsigned char v = mraw[i];
        if (v == 0x3F) s_float = 1;
        if (v != 0 && (i & 3) != 0) s_odd = 1;
    }
    __syncthreads();
    const int dtype = s_float ? 2 : (s_odd ? 0 : 1);

    const int m0 = blockIdx.x * 256 + threadIdx.x;
    for (int m = m0; m < BT; m += 64 * 256) {
        unsigned char r;
        if (dtype == 0)      r = (mraw[m] != 0);
        else if (dtype == 1) r = (((const int*)mraw)[m] != 0);
        else                 r = (((const float*)mraw)[m] != 0.0f);
        g_mask[m] = r;
    }
}

// ---------------------------------------------------------------------------
// kv partial, register-blocked 4d x 16e per thread. grid (BH, 8).
// ---------------------------------------------------------------------------
__global__ __launch_bounds__(256) void kv_partial_kernel()
{
    const int tid = threadIdx.x;
    const int bh = blockIdx.x, sy = blockIdx.y;
    const int b = bh >> 4, h = bh & 15;
    const int t0 = sy * 512;

    __shared__ __align__(16) float Ks[2][32][64];
    __shared__ __align__(16) float Vs[2][32][64];
    const uint32_t sK = smem_u32(&Ks[0][0][0]);
    const uint32_t sV = smem_u32(&Vs[0][0][0]);

    const int q  = tid >> 6;
    const int r  = tid & 63;
    const int d0 = (r >> 2) * 4;
    const int e0 = (r & 3) * 16;

    float acc[4][16];
#pragma unroll
    for (int j = 0; j < 4; j++)
#pragma unroll
        for (int i = 0; i < 16; i++) acc[j][i] = 0.f;
    float ks[4] = {0.f, 0.f, 0.f, 0.f};

    const size_t base = ((size_t)b * Tc) * Dc + h * 64;

    const int tl0 = tid >> 4,         c40 = (tid & 15) * 4;
    const int tl1 = (tid + 256) >> 4, c41 = ((tid + 256) & 15) * 4;
    const uint32_t so0 = (uint32_t)((tl0 * 64 + c40) * 4);
    const uint32_t so1 = (uint32_t)((tl1 * 64 + c41) * 4);

    auto load_chunk = [&](int c, int bufsel) {
        uint32_t kb = sK + bufsel * 8192, vb = sV + bufsel * 8192;
        size_t g0 = base + (size_t)(t0 + c * 32 + tl0) * Dc + c40;
        size_t g1 = base + (size_t)(t0 + c * 32 + tl1) * Dc + c41;
        cp16(kb + so0, g_k + g0);
        cp16(vb + so0, g_v + g0);
        cp16(kb + so1, g_k + g1);
        cp16(vb + so1, g_v + g1);
    };

    load_chunk(0, 0);
    CP_COMMIT();

#pragma unroll 1
    for (int c = 0; c < 16; c++) {
        if (c < 15) {
            load_chunk(c + 1, (c + 1) & 1);
            CP_COMMIT();
            CP_WAIT1();
        } else {
            CP_WAIT0();
        }
        __syncthreads();
        const int cb = c & 1;
#pragma unroll
        for (int tt = 0; tt < 8; tt++) {
            const int t = q * 8 + tt;
            float4 kd = *(const float4*)&Ks[cb][t][d0];
            float4 v0 = *(const float4*)&Vs[cb][t][e0];
            float4 v1 = *(const float4*)&Vs[cb][t][e0 + 4];
            float4 v2 = *(const float4*)&Vs[cb][t][e0 + 8];
            float4 v3 = *(const float4*)&Vs[cb][t][e0 + 12];
            ks[0] += kd.x; ks[1] += kd.y; ks[2] += kd.z; ks[3] += kd.w;
            const float kv4[4] = {kd.x, kd.y, kd.z, kd.w};
            const float vv[16] = {v0.x, v0.y, v0.z, v0.w, v1.x, v1.y, v1.z, v1.w,
                                  v2.x, v2.y, v2.z, v2.w, v3.x, v3.y, v3.z, v3.w};
#pragma unroll
            for (int j = 0; j < 4; j++)
#pragma unroll
                for (int i = 0; i < 16; i++)
                    acc[j][i] = fmaf(kv4[j], vv[i], acc[j][i]);
        }
        __syncthreads();
    }

    const int slot = bh * SPLIT + sy * 4 + q;
    float* outp = g_kvp + (size_t)slot * 4096;
#pragma unroll
    for (int j = 0; j < 4; j++) {
        float* rp = outp + (d0 + j) * 64 + e0;
        *(float4*)(rp + 0)  = make_float4(acc[j][0], acc[j][1], acc[j][2], acc[j][3]);
        *(float4*)(rp + 4)  = make_float4(acc[j][4], acc[j][5], acc[j][6], acc[j][7]);
        *(float4*)(rp + 8)  = make_float4(acc[j][8], acc[j][9], acc[j][10], acc[j][11]);
        *(float4*)(rp + 12) = make_float4(acc[j][12], acc[j][13], acc[j][14], acc[j][15]);
    }
    if ((r & 3) == 0) {
#pragma unroll
        for (int j = 0; j < 4; j++)
            g_ksp[slot * 64 + d0 + j] = ks[j];
    }
}

// ---------------------------------------------------------------------------
__global__ __launch_bounds__(256) void kv_reduce_kernel()
{
    const int bh = blockIdx.x, tid = threadIdx.x;
#pragma unroll
    for (int j = 0; j < 4; j++) {
        int off = tid * 16 + j * 4;
        float4 s = make_float4(0.f, 0.f, 0.f, 0.f);
#pragma unroll
        for (int sp = 0; sp < SPLIT; sp++) {
            float4 p = *(const float4*)(g_kvp + ((size_t)(bh * SPLIT + sp)) * 4096 + off);
            s.x += p.x; s.y += p.y; s.z += p.z; s.w += p.w;
        }
        *(float4*)(g_kv + (size_t)bh * 4096 + off) = s;
    }
    if (tid < 64) {
        float s = 0.f;
#pragma unroll
        for (int sp = 0; sp < SPLIT; sp++)
            s += g_ksp[(bh * SPLIT + sp) * 64 + tid];
        g_ksum[bh * 64 + tid] = s;
    }
}

// ---------------------------------------------------------------------------
// attn out, register-blocked 4 t-rows x 16 e-cols; writes bf16 hi/lo split.
// ---------------------------------------------------------------------------
constexpr int QS_STRIDE = 260;

__global__ __launch_bounds__(256) void attn_out_kernel()
{
    const int tid = threadIdx.x;
    const int bh = blockIdx.y;
    const int b = bh >> 4, h = bh & 15;
    const int t0 = blockIdx.x * 256;

    __shared__ __align__(16) float KV[4096];
    __shared__ __align__(16) float Qs[16][QS_STRIDE];
    __shared__ float Ksm[64];

#pragma unroll
    for (int j = 0; j < 4; j++) {
        int f = tid + j * 256;
        *(float4*)&KV[f * 4] = *(const float4*)(g_kv + (size_t)bh * 4096 + f * 4);
    }
    if (tid < 64) Ksm[tid] = g_ksum[bh * 64 + tid];

    const size_t base = ((size_t)b * Tc) * Dc + h * 64;
    const int tl4 = tid >> 2;
    const int e0 = (tid & 3) * 16;

    float acc[4][16];
#pragma unroll
    for (int j = 0; j < 4; j++)
#pragma unroll
        for (int i = 0; i < 16; i++) acc[j][i] = 0.f;
    float nrm[4] = {0.f, 0.f, 0.f, 0.f};

#pragma unroll 1
    for (int dc = 0; dc < 4; dc++) {
        __syncthreads();
#pragma unroll
        for (int j = 0; j < 16; j++) {
            int idx = tid + j * 256;
            int d = idx & 15, t = idx >> 4;
            Qs[d][t] = g_q[base + (size_t)(t0 + t) * Dc + dc * 16 + d];
        }
        __syncthreads();
#pragma unroll
        for (int d2 = 0; d2 < 16; d2++) {
            const int dg = dc * 16 + d2;
            float4 qv = *(const float4*)&Qs[d2][tl4 * 4];
            const float km = Ksm[dg];
            const float4* kvp = (const float4*)&KV[dg * 64 + e0];
            float4 w0 = kvp[0], w1 = kvp[1], w2 = kvp[2], w3 = kvp[3];
            const float qq[4] = {qv.x, qv.y, qv.z, qv.w};
            const float vv[16] = {w0.x, w0.y, w0.z, w0.w, w1.x, w1.y, w1.z, w1.w,
                                  w2.x, w2.y, w2.z, w2.w, w3.x, w3.y, w3.z, w3.w};
#pragma unroll
            for (int j = 0; j < 4; j++) {
                nrm[j] = fmaf(qq[j], km, nrm[j]);
#pragma unroll
                for (int i = 0; i < 16; i++)
                    acc[j][i] = fmaf(qq[j], vv[i], acc[j][i]);
            }
        }
    }

#pragma unroll
    for (int j = 0; j < 4; j++) {
        const float inv = 1.f / fmaxf(nrm[j], 1e-6f);
        const size_t idx = base + (size_t)(t0 + tl4 * 4 + j) * Dc + e0;
#pragma unroll
        for (int g = 0; g < 4; g++) {
            float a0 = acc[j][g * 4 + 0] * inv, a1 = acc[j][g * 4 + 1] * inv;
            float a2 = acc[j][g * 4 + 2] * inv, a3 = acc[j][g * 4 + 3] * inv;
            float h0 = __bfloat162float(__float2bfloat16(a0));
            float h1 = __bfloat162float(__float2bfloat16(a1));
            float h2 = __bfloat162float(__float2bfloat16(a2));
            float h3 = __bfloat162float(__float2bfloat16(a3));
            *(uint2*)(g_ah + idx + g * 4) = make_uint2(pack_bf2(a0, a1), pack_bf2(a2, a3));
            *(uint2*)(g_al + idx + g * 4) = make_uint2(pack_bf2(a0 - h0, a1 - h1),
                                                       pack_bf2(a2 - h2, a3 - h3));
        }
    }
}

// ---------------------------------------------------------------------------
extern "C" void kernel_launch(void* const* d_in, const int* in_sizes, int n_in,
                              void* d_out, int out_size)
{
    const float* x          = (const float*)d_in[0];
    const unsigned char* mk = (const unsigned char*)d_in[1];
    float* out              = (float*)d_out;

    float *qp, *kp, *vp;
    unsigned char* mkc;
    __nv_bfloat16 *xh, *xl, *ah, *al, *wh, *wl;
    cudaGetSymbolAddress((void**)&qp, g_q);
    cudaGetSymbolAddress((void**)&kp, g_k);
    cudaGetSymbolAddress((void**)&vp, g_v);
    cudaGetSymbolAddress((void**)&mkc, g_mask);
    cudaGetSymbolAddress((void**)&xh, g_xh);
    cudaGetSymbolAddress((void**)&xl, g_xl);
    cudaGetSymbolAddress((void**)&ah, g_ah);
    cudaGetSymbolAddress((void**)&al, g_al);
    cudaGetSymbolAddress((void**)&wh, g_wh);
    cudaGetSymbolAddress((void**)&wl, g_wl);

    cudaFuncSetAttribute(gemm_kv_kernel,
                         cudaFuncAttributeMaxDynamicSharedMemorySize, GSM_TOTAL);
    cudaFuncSetAttribute(gemm_tc_kernel,
                         cudaFuncAttributeMaxDynamicSharedMemorySize, GSM_TOTAL);

    // Side stream + events (created once; host-side only; identical work per call).
    static cudaStream_t s1 = nullptr;
    static cudaEvent_t evFork = nullptr, evX = nullptr, evPrep = nullptr, evJoin = nullptr;
    if (s1 == nullptr) {
        cudaStreamCreateWithFlags(&s1, cudaStreamNonBlocking);
        cudaEventCreateWithFlags(&evFork, cudaEventDisableTiming);
        cudaEventCreateWithFlags(&evX, cudaEventDisableTiming);
        cudaEventCreateWithFlags(&evPrep, cudaEventDisableTiming);
        cudaEventCreateWithFlags(&evJoin, cudaEventDisableTiming);
    }

    const int n4x = BT * Dc / 4;

    // Fork side stream from stream 0 (capture-safe: s1 first waits on s0 event).
    cudaEventRecord(evFork, 0);
    cudaStreamWaitEvent(s1, evFork, 0);

    // s1: W splits + mask (independent of x).
    splitw_kernel<<<dim3(512, 2), 256, 0, s1>>>((const float4*)d_in[2], (const float4*)d_in[3], 0);
    splitw_kernel<<<dim3(512, 2), 256, 0, s1>>>((const float4*)d_in[4], (const float4*)d_in[5], 2);
    mask_convert_kernel<<<64, 256, 0, s1>>>(mk);
    cudaEventRecord(evPrep, s1);

    // s0: x split halves (concurrent with s1 prep).
    split_kernel<<<2048, 256>>>((const float4*)x, (uint2*)xh, (uint2*)xl, 0, n4x / 2);
    split_kernel<<<2048, 256>>>((const float4*)x, (uint2*)xh, (uint2*)xl, n4x / 2, n4x);
    cudaEventRecord(evX, 0);

    // s1: Q GEMM, concurrent with KV GEMM on s0 (needs x split + W0 split).
    cudaStreamWaitEvent(s1, evX, 0);
    gemm_tc_kernel<<<dim3(8, 128), 256, GSM_TOTAL, s1>>>(
        xh, xl, wh + 0 * (size_t)Dc * Dc, wl + 0 * (size_t)Dc * Dc, qp, mkc, 1);
    cudaEventRecord(evJoin, s1);

    // s0: KV GEMM (needs x split on s0 + W1/W2 splits + mask from s1), then kv chain.
    cudaStreamWaitEvent(0, evPrep, 0);
    gemm_kv_kernel<<<dim3(16, 128), 256, GSM_TOTAL>>>(xh, xl, kp, vp, mkc);
    kv_partial_kernel<<<dim3(BH, 8), 256>>>();
    kv_reduce_kernel<<<BH, 256>>>();

    // Join: attn_out needs Q.
    cudaStreamWaitEvent(0, evJoin, 0);
    attn_out_kernel<<<dim3(Tc / 256, BH), 256>>>();
    gemm_tc_kernel<<<dim3(8, 128), 256, GSM_TOTAL>>>(
        ah, al, wh + 3 * (size_t)Dc * Dc, wl + 3 * (size_t)Dc * Dc, out, mkc, 0);
}